// round 3
// baseline (speedup 1.0000x reference)
#include <cuda_runtime.h>

#define NN 207
#define EE 1722
#define TT 24
#define BB 64
#define LL 2048
#define RESV 12
#define L4 (LL / 4)      // 512 float4 per row
#define LT4 32           // float4 per L-tile (= 128 floats)
#define NTHREADS 256
#define NCHUNK 4
#define CHSZ ((EE + NCHUNK - 1) / NCHUNK)   // 431

// ---------------- device scratch (no allocation allowed) ----------------
struct __align__(16) EF { float wrn; float wra; int noff; int pad; };  // wrn = -wr
struct __align__(8)  ET { float wdc; int noff; };

__device__ EF     g_ef[TT * EE];      // from-CSR ordered, per t (reaction gathers)
__device__ ET     g_et[TT * EE];      // to-CSR ordered, per t (diffusion gathers)
__device__ float4 g_c1[TT * NN];      // (dr, dra, dd+dda+1, br)
__device__ float2 g_c2[TT * NN];      // (bra, bd+bda)
__device__ int    g_from_off[NN + 1];
__device__ int    g_to_off[NN + 1];
__device__ int    g_from_idx[EE];     // CSR slot -> edge id (sorted within bucket)
__device__ int    g_to_idx[EE];
__device__ int    g_fnoff[EE];        // edge_to * LT4 per from-CSR slot
__device__ int    g_tnoff[EE];        // edge_from * LT4 per to-CSR slot

// ---------------- f32x2 packed helpers ----------------
__device__ __forceinline__ unsigned long long pk2(float a, float b) {
    unsigned long long r;
    asm("mov.b64 %0, {%1, %2};" : "=l"(r) : "f"(a), "f"(b));
    return r;
}
__device__ __forceinline__ void upk2(unsigned long long v, float& a, float& b) {
    asm("mov.b64 {%0, %1}, %2;" : "=f"(a), "=f"(b) : "l"(v));
}
// d = a*b + d  (packed 2xf32, single FFMA2)
__device__ __forceinline__ void fma2(unsigned long long& d,
                                     unsigned long long a, unsigned long long b) {
    asm("fma.rn.f32x2 %0, %1, %2, %0;" : "+l"(d) : "l"(a), "l"(b));
}
__device__ __forceinline__ float ftanh(float x) {
    float y;
    asm("tanh.approx.f32 %0, %1;" : "=f"(y) : "f"(x));
    return y;
}

// ---------------- prepass 1: deterministic parallel CSR build ----------------
// Chunked counting sort: thread (w, c) counts/fills node w's matches in edge
// chunk c. Fully deterministic (order = edge id order), no atomics, no sorting.
__global__ __launch_bounds__(NN * NCHUNK)
void rd_build_csr(const int* __restrict__ ef, const int* __restrict__ et) {
    __shared__ int sf[EE], st[EE];
    __shared__ int cnt[NN][NCHUNK];
    __shared__ int base[NN][NCHUNK];
    __shared__ int tot[NN];
    __shared__ int off[NN + 1];
    const int tid = threadIdx.x;
    const int w = tid >> 2, c = tid & (NCHUNK - 1);
    const int lo = c * CHSZ, hi = (lo + CHSZ < EE) ? lo + CHSZ : EE;

    for (int i = tid; i < EE; i += blockDim.x) { sf[i] = ef[i]; st[i] = et[i]; }
    __syncthreads();

    // ===== FROM phase =====
    if (w < NN) {
        int n = 0;
        for (int i = lo; i < hi; i++) n += (sf[i] == w);
        cnt[w][c] = n;
    }
    __syncthreads();
    if (w < NN && c == 0) tot[w] = cnt[w][0] + cnt[w][1] + cnt[w][2] + cnt[w][3];
    __syncthreads();
    if (tid == 0) {
        int a = 0;
        for (int i = 0; i < NN; i++) { off[i] = a; a += tot[i]; }
        off[NN] = a;
    }
    __syncthreads();
    if (w < NN) {
        int p = off[w];
        for (int cc = 0; cc < c; cc++) p += cnt[w][cc];
        base[w][c] = p;
    }
    __syncthreads();
    if (w < NN) {
        int p = base[w][c];
        for (int i = lo; i < hi; i++) {
            if (sf[i] == w) {
                g_from_idx[p] = i;
                g_fnoff[p] = st[i] * LT4;
                p++;
            }
        }
        if (c == 0) g_from_off[w] = off[w];
        if (tid == 0) g_from_off[NN] = off[NN];
    }
    __syncthreads();

    // ===== TO phase =====
    if (w < NN) {
        int n = 0;
        for (int i = lo; i < hi; i++) n += (st[i] == w);
        cnt[w][c] = n;
    }
    __syncthreads();
    if (w < NN && c == 0) tot[w] = cnt[w][0] + cnt[w][1] + cnt[w][2] + cnt[w][3];
    __syncthreads();
    if (tid == 0) {
        int a = 0;
        for (int i = 0; i < NN; i++) { off[i] = a; a += tot[i]; }
        off[NN] = a;
    }
    __syncthreads();
    if (w < NN) {
        int p = off[w];
        for (int cc = 0; cc < c; cc++) p += cnt[w][cc];
        base[w][c] = p;
    }
    __syncthreads();
    if (w < NN) {
        int p = base[w][c];
        for (int i = lo; i < hi; i++) {
            if (st[i] == w) {
                g_to_idx[p] = i;
                g_tnoff[p] = sf[i] * LT4;
                p++;
            }
        }
        if (c == 0) g_to_off[w] = off[w];
        if (tid == 0) g_to_off[NN] = off[NN];
    }
}

// ---------------- prepass 2: per-t packed weights + diagonals ----------------
// Per output row w (time slot t):
//   reaction   = (Σ_{to=w} wr) x[w]  − Σ_{from=w} wr  x[to]  + br
//   reaction_a = (Σ_{to=w} wra) x[w] + Σ_{from=w} wra x[to]  + bra  (diag=0 if b==0)
//   linear     = (Σ_{from=w}(wd+wda) + 1) x[w] + Σ_{to=w}(wda−wd) x[from] + bd + bda
__global__ __launch_bounds__(512)
void rd_prep(const float* __restrict__ wr,  const float* __restrict__ wd,
             const float* __restrict__ wra, const float* __restrict__ wda,
             const float* __restrict__ br,  const float* __restrict__ bd,
             const float* __restrict__ bra, const float* __restrict__ bda) {
    const int t = blockIdx.x;
    const int tid = threadIdx.x;
    const int tE = t * EE;

    // CSR-slot-parallel record packing (coalesced writes)
    for (int k = tid; k < EE; k += 512) {
        int e = g_from_idx[k];
        EF rec; rec.wrn = -wr[tE + e]; rec.wra = wra[tE + e];
        rec.noff = g_fnoff[k]; rec.pad = 0;
        g_ef[tE + k] = rec;
    }
    for (int k = tid; k < EE; k += 512) {
        int e = g_to_idx[k];
        ET rec; rec.wdc = wda[tE + e] - wd[tE + e]; rec.noff = g_tnoff[k];
        g_et[tE + k] = rec;
    }
    __syncthreads();

    // node-parallel deterministic diagonal sums (reads are L2/L1 hot now)
    if (tid < NN) {
        const int w = tid;
        float dd = 0.f, dda = 0.f;
        for (int k = g_from_off[w]; k < g_from_off[w + 1]; k++) {
            int e = g_from_idx[k];
            dd += wd[tE + e]; dda += wda[tE + e];
        }
        float dr = 0.f, dra = 0.f;
        for (int k = g_to_off[w]; k < g_to_off[w + 1]; k++) {
            int e = g_to_idx[k];
            dr += wr[tE + e]; dra += wra[tE + e];
        }
        float4 c1; c1.x = dr; c1.y = dra; c1.z = dd + dda + 1.f; c1.w = br[t * NN + w];
        g_c1[t * NN + w] = c1;
        float2 c2; c2.x = bra[t * NN + w]; c2.y = bd[t * NN + w] + bda[t * NN + w];
        g_c2[t * NN + w] = c2;
    }
}

// ---------------- main kernel ----------------
__global__ __launch_bounds__(NTHREADS, 2)
void rd_main(const float* __restrict__ X, const int* __restrict__ ind,
             float* __restrict__ out) {
    extern __shared__ float4 xs4[];   // [NN][LT4]
    const ulonglong2* __restrict__ xsp = reinterpret_cast<const ulonglong2*>(xs4);
    const int b   = blockIdx.y;
    const int l0q = blockIdx.x * LT4;
    const int t   = ind[b] / RESV;
    const int tid = threadIdx.x;

    // load x tile: inputs[b, 0, :, l0:l0+128]
    const float4* xb4 = reinterpret_cast<const float4*>(X)
                        + (size_t)b * 2 * NN * L4 + l0q;
    for (int idx = tid; idx < NN * LT4; idx += NTHREADS) {
        int w = idx >> 5, c = idx & (LT4 - 1);
        xs4[idx] = xb4[(size_t)w * L4 + c];
    }
    __syncthreads();

    const int lane = tid & 31;
    const int wg   = tid >> 5;
    const bool b0  = (b == 0);
    float4* ob4 = reinterpret_cast<float4*>(out) + (size_t)b * NN * L4 + l0q + lane;
    const EF* __restrict__ efp = g_ef + t * EE;
    const ET* __restrict__ etp = g_et + t * EE;

    for (int w = wg; w < NN; w += NTHREADS / 32) {
        ulonglong2 xw = xsp[w * LT4 + lane];
        float4 c1 = g_c1[t * NN + w];
        float2 c2 = g_c2[t * NN + w];
        float dra = b0 ? 0.f : c1.y;   // batch 0: RWa diagonal is exactly zero

        unsigned long long drp  = pk2(c1.x, c1.x), brp  = pk2(c1.w, c1.w);
        unsigned long long drap = pk2(dra,  dra ), brap = pk2(c2.x, c2.x);
        unsigned long long dlp  = pk2(c1.z, c1.z), bdp  = pk2(c2.y, c2.y);

        unsigned long long r01 = brp,  r23 = brp;
        unsigned long long ra01 = brap, ra23 = brap;
        unsigned long long li01 = bdp,  li23 = bdp;
        fma2(r01, drp, xw.x);   fma2(r23, drp, xw.y);
        fma2(ra01, drap, xw.x); fma2(ra23, drap, xw.y);
        fma2(li01, dlp, xw.x);  fma2(li23, dlp, xw.y);

        int k0 = g_from_off[w], k1 = g_from_off[w + 1];
        #pragma unroll 2
        for (int k = k0; k < k1; k++) {
            EF e = efp[k];
            ulonglong2 xv = xsp[e.noff + lane];
            unsigned long long wrp  = pk2(e.wrn, e.wrn);
            unsigned long long wrap = pk2(e.wra, e.wra);
            fma2(r01, wrp, xv.x);   fma2(r23, wrp, xv.y);
            fma2(ra01, wrap, xv.x); fma2(ra23, wrap, xv.y);
        }

        k0 = g_to_off[w]; k1 = g_to_off[w + 1];
        #pragma unroll 2
        for (int k = k0; k < k1; k++) {
            ET e = etp[k];
            ulonglong2 xv = xsp[e.noff + lane];
            unsigned long long wdp = pk2(e.wdc, e.wdc);
            fma2(li01, wdp, xv.x); fma2(li23, wdp, xv.y);
        }

        float r0, r1, r2, r3, a0, a1, a2, a3, l0, l1, l2, l3;
        upk2(r01, r0, r1);   upk2(r23, r2, r3);
        upk2(ra01, a0, a1);  upk2(ra23, a2, a3);
        upk2(li01, l0, l1);  upk2(li23, l2, l3);

        float4 o;
        o.x = ftanh(r0) + ftanh(a0) + l0;
        o.y = ftanh(r1) + ftanh(a1) + l1;
        o.z = ftanh(r2) + ftanh(a2) + l2;
        o.w = ftanh(r3) + ftanh(a3) + l3;
        ob4[(size_t)w * L4] = o;
    }
}

// ---------------- launch ----------------
extern "C" void kernel_launch(void* const* d_in, const int* in_sizes, int n_in,
                              void* d_out, int out_size) {
    const float* X   = (const float*)d_in[0];
    const int*   ind = (const int*)d_in[1];
    const int*   ef  = (const int*)d_in[2];
    const int*   et  = (const int*)d_in[3];
    const float* wr  = (const float*)d_in[4];
    const float* wd  = (const float*)d_in[5];
    const float* wra = (const float*)d_in[6];
    const float* wda = (const float*)d_in[7];
    const float* br  = (const float*)d_in[8];
    const float* bd  = (const float*)d_in[9];
    const float* bra = (const float*)d_in[10];
    const float* bda = (const float*)d_in[11];
    float* out = (float*)d_out;

    const int smem = NN * LT4 * (int)sizeof(float4);   // 105,984 B
    cudaFuncSetAttribute(rd_main, cudaFuncAttributeMaxDynamicSharedMemorySize, smem);

    rd_build_csr<<<1, NN * NCHUNK>>>(ef, et);
    rd_prep<<<TT, 512>>>(wr, wd, wra, wda, br, bd, bra, bda);

    dim3 grid(LL / (LT4 * 4), BB);   // (16, 64)
    rd_main<<<grid, NTHREADS, smem>>>(X, ind, out);
}

// round 4
// speedup vs baseline: 1.3112x; 1.3112x over previous
#include <cuda_runtime.h>

#define NN 207
#define EE 1722
#define TT 24
#define BB 64
#define LL 2048
#define RESV 12
#define L4 (LL / 4)      // 512 float4 per row
#define LT4 32           // float4 per L-tile (= 128 floats)
#define NTHREADS 256

// ---------------- device scratch (no allocation allowed) ----------------
struct __align__(16) EF { float wrn; float wra; int noff; int pad; };  // wrn = -wr
struct __align__(8)  ET { float wdc; int noff; };

__device__ EF     g_ef[TT * EE];      // from-CSR ordered, per t (reaction gathers)
__device__ ET     g_et[TT * EE];      // to-CSR ordered, per t (diffusion gathers)
__device__ float4 g_c1[TT * NN];      // (dr, dra, dd+dda+1, br)
__device__ float2 g_c2[TT * NN];      // (bra, bd+bda)
__device__ int    g_from_off[NN + 1];
__device__ int    g_to_off[NN + 1];

// ---------------- f32x2 packed helpers ----------------
__device__ __forceinline__ unsigned long long pk2(float a, float b) {
    unsigned long long r;
    asm("mov.b64 %0, {%1, %2};" : "=l"(r) : "f"(a), "f"(b));
    return r;
}
__device__ __forceinline__ void upk2(unsigned long long v, float& a, float& b) {
    asm("mov.b64 {%0, %1}, %2;" : "=f"(a), "=f"(b) : "l"(v));
}
__device__ __forceinline__ void fma2(unsigned long long& d,
                                     unsigned long long a, unsigned long long b) {
    asm("fma.rn.f32x2 %0, %1, %2, %0;" : "+l"(d) : "l"(a), "l"(b));
}
__device__ __forceinline__ float ftanh(float x) {
    float y;
    asm("tanh.approx.f32 %0, %1;" : "=f"(y) : "f"(x));
    return y;
}

// =====================================================================
// Fused prepass: one block per time slot t. Each block deterministically
// rebuilds the CSR in its own shared memory (redundant but parallel),
// then packs that t's edge records + diagonals.
// =====================================================================
__global__ __launch_bounds__(NTHREADS)
void rd_prep_all(const int* __restrict__ ef, const int* __restrict__ et,
                 const float* __restrict__ wr,  const float* __restrict__ wd,
                 const float* __restrict__ wra, const float* __restrict__ wda,
                 const float* __restrict__ br,  const float* __restrict__ bd,
                 const float* __restrict__ bra, const float* __restrict__ bda) {
    extern __shared__ int sh[];
    int*   sf    = sh;                 // [EE]
    int*   st    = sf    + EE;         // [EE]
    int*   slotF = st    + EE;         // [EE]
    int*   slotT = slotF + EE;         // [EE]
    float* dsum  = (float*)(slotT + EE);   // [EE] wd+wda by from-slot
    float* rs_r  = dsum  + EE;         // [EE] wr  by to-slot
    float* rs_ra = rs_r  + EE;         // [EE] wra by to-slot
    int*   cntF  = (int*)(rs_ra + EE); // [NN]
    int*   cntT  = cntF + NN;          // [NN]
    int*   offF  = cntT + NN;          // [NN+1]
    int*   offT  = offF + NN + 1;      // [NN+1]
    int*   runF  = offT + NN + 1;      // [NN]
    int*   runT  = runF + NN;          // [NN]

    const int t   = blockIdx.x;
    const int tid = threadIdx.x;
    const int lane = tid & 31;
    const int wid  = tid >> 5;
    const int tE  = t * EE;

    for (int i = tid; i < EE; i += NTHREADS) { sf[i] = ef[i]; st[i] = et[i]; }
    for (int i = tid; i < NN; i += NTHREADS) { cntF[i] = 0; cntT[i] = 0; runF[i] = 0; runT[i] = 0; }
    __syncthreads();

    // edge-parallel counts (integer atomics: order-independent, deterministic)
    for (int i = tid; i < EE; i += NTHREADS) {
        atomicAdd(&cntF[sf[i]], 1);
        atomicAdd(&cntT[st[i]], 1);
    }
    __syncthreads();

    // warp 0: exclusive prefix over cntF; warp 1: over cntT (shuffle scan)
    if (wid < 2) {
        const int* cnt = wid ? cntT : cntF;
        int* off = wid ? offT : offF;
        int carry = 0;
        #pragma unroll
        for (int j = 0; j < (NN + 31) / 32; j++) {
            int idx = j * 32 + lane;
            int v = (idx < NN) ? cnt[idx] : 0;
            int s = v;
            #pragma unroll
            for (int d = 1; d < 32; d <<= 1) {
                int u = __shfl_up_sync(0xffffffffu, s, d);
                if (lane >= d) s += u;
            }
            int tot = __shfl_sync(0xffffffffu, s, 31);
            if (idx < NN) off[idx] = carry + s - v;
            carry += tot;
        }
        if (lane == 0) off[NN] = carry;
    }
    __syncthreads();

    // deterministic slot assignment: warp 0 ranks from-edges, warp 1 to-edges.
    // Chunks of 32 edges processed in order; within a chunk, match_any groups
    // lanes by node, rank = popc of earlier lanes; leader advances running count.
    if (wid < 2) {
        const int* key = wid ? st : sf;
        const int* off = wid ? offT : offF;
        int* run  = wid ? runT : runF;
        int* slot = wid ? slotT : slotF;
        const int nch = (EE + 31) / 32;
        for (int c = 0; c < nch; c++) {
            int i = c * 32 + lane;
            int f = (i < EE) ? key[i] : (NN + lane);   // distinct dummies
            unsigned m = __match_any_sync(0xffffffffu, f);
            int leader = __ffs(m) - 1;
            int rank = __popc(m & ((1u << lane) - 1u));
            int base = 0;
            if (lane == leader && f < NN) { base = run[f]; run[f] = base + __popc(m); }
            base = __shfl_sync(0xffffffffu, base, leader);
            if (i < EE) slot[i] = off[f] + base + rank;
        }
    }
    __syncthreads();

    // edge-parallel packing (coalesced weight reads)
    for (int i = tid; i < EE; i += NTHREADS) {
        float wrv  = wr[tE + i],  wrav = wra[tE + i];
        float wdv  = wd[tE + i],  wdav = wda[tE + i];
        int sF = slotF[i], sT = slotT[i];
        EF rf; rf.wrn = -wrv; rf.wra = wrav; rf.noff = st[i] * LT4; rf.pad = 0;
        g_ef[tE + sF] = rf;
        ET rt; rt.wdc = wdav - wdv; rt.noff = sf[i] * LT4;
        g_et[tE + sT] = rt;
        dsum[sF]  = wdv + wdav;
        rs_r[sT]  = wrv;
        rs_ra[sT] = wrav;
    }
    __syncthreads();

    // node-parallel deterministic diagonal sums (fixed bucket order)
    if (tid < NN) {
        const int w = tid;
        float dd1 = 0.f;
        for (int k = offF[w]; k < offF[w + 1]; k++) dd1 += dsum[k];
        float dr = 0.f, dra = 0.f;
        for (int k = offT[w]; k < offT[w + 1]; k++) { dr += rs_r[k]; dra += rs_ra[k]; }
        float4 c1; c1.x = dr; c1.y = dra; c1.z = dd1 + 1.f; c1.w = br[t * NN + w];
        g_c1[t * NN + w] = c1;
        float2 c2; c2.x = bra[t * NN + w]; c2.y = bd[t * NN + w] + bda[t * NN + w];
        g_c2[t * NN + w] = c2;
    }

    // one block publishes the (identical) global offsets for rd_main
    if (t == 0 && tid <= NN) {
        g_from_off[tid] = offF[tid];
        g_to_off[tid]   = offT[tid];
    }
}

// =====================================================================
// Main kernel
// =====================================================================
__global__ __launch_bounds__(NTHREADS, 2)
void rd_main(const float* __restrict__ X, const int* __restrict__ ind,
             float* __restrict__ out) {
    extern __shared__ float4 xs4[];   // [NN][LT4]
    const ulonglong2* __restrict__ xsp = reinterpret_cast<const ulonglong2*>(xs4);
    const int b   = blockIdx.y;
    const int l0q = blockIdx.x * LT4;
    const int t   = ind[b] / RESV;
    const int tid = threadIdx.x;

    const float4* xb4 = reinterpret_cast<const float4*>(X)
                        + (size_t)b * 2 * NN * L4 + l0q;
    for (int idx = tid; idx < NN * LT4; idx += NTHREADS) {
        int w = idx >> 5, c = idx & (LT4 - 1);
        xs4[idx] = xb4[(size_t)w * L4 + c];
    }
    __syncthreads();

    const int lane = tid & 31;
    const int wg   = tid >> 5;
    const bool b0  = (b == 0);
    float4* ob4 = reinterpret_cast<float4*>(out) + (size_t)b * NN * L4 + l0q + lane;
    const EF* __restrict__ efp = g_ef + t * EE;
    const ET* __restrict__ etp = g_et + t * EE;

    for (int w = wg; w < NN; w += NTHREADS / 32) {
        ulonglong2 xw = xsp[w * LT4 + lane];
        float4 c1 = g_c1[t * NN + w];
        float2 c2 = g_c2[t * NN + w];
        float dra = b0 ? 0.f : c1.y;   // batch 0: RWa diagonal is exactly zero

        unsigned long long drp  = pk2(c1.x, c1.x), brp  = pk2(c1.w, c1.w);
        unsigned long long drap = pk2(dra,  dra ), brap = pk2(c2.x, c2.x);
        unsigned long long dlp  = pk2(c1.z, c1.z), bdp  = pk2(c2.y, c2.y);

        unsigned long long r01 = brp,  r23 = brp;
        unsigned long long ra01 = brap, ra23 = brap;
        unsigned long long li01 = bdp,  li23 = bdp;
        fma2(r01, drp, xw.x);   fma2(r23, drp, xw.y);
        fma2(ra01, drap, xw.x); fma2(ra23, drap, xw.y);
        fma2(li01, dlp, xw.x);  fma2(li23, dlp, xw.y);

        int k0 = g_from_off[w], k1 = g_from_off[w + 1];
        #pragma unroll 4
        for (int k = k0; k < k1; k++) {
            EF e = efp[k];
            ulonglong2 xv = xsp[e.noff + lane];
            unsigned long long wrp  = pk2(e.wrn, e.wrn);
            unsigned long long wrap = pk2(e.wra, e.wra);
            fma2(r01, wrp, xv.x);   fma2(r23, wrp, xv.y);
            fma2(ra01, wrap, xv.x); fma2(ra23, wrap, xv.y);
        }

        k0 = g_to_off[w]; k1 = g_to_off[w + 1];
        #pragma unroll 4
        for (int k = k0; k < k1; k++) {
            ET e = etp[k];
            ulonglong2 xv = xsp[e.noff + lane];
            unsigned long long wdp = pk2(e.wdc, e.wdc);
            fma2(li01, wdp, xv.x); fma2(li23, wdp, xv.y);
        }

        float r0, r1, r2, r3, a0, a1, a2, a3, l0, l1, l2, l3;
        upk2(r01, r0, r1);   upk2(r23, r2, r3);
        upk2(ra01, a0, a1);  upk2(ra23, a2, a3);
        upk2(li01, l0, l1);  upk2(li23, l2, l3);

        float4 o;
        o.x = ftanh(r0) + ftanh(a0) + l0;
        o.y = ftanh(r1) + ftanh(a1) + l1;
        o.z = ftanh(r2) + ftanh(a2) + l2;
        o.w = ftanh(r3) + ftanh(a3) + l3;
        ob4[(size_t)w * L4] = o;
    }
}

// ---------------- launch ----------------
extern "C" void kernel_launch(void* const* d_in, const int* in_sizes, int n_in,
                              void* d_out, int out_size) {
    const float* X   = (const float*)d_in[0];
    const int*   ind = (const int*)d_in[1];
    const int*   ef  = (const int*)d_in[2];
    const int*   et  = (const int*)d_in[3];
    const float* wr  = (const float*)d_in[4];
    const float* wd  = (const float*)d_in[5];
    const float* wra = (const float*)d_in[6];
    const float* wda = (const float*)d_in[7];
    const float* br  = (const float*)d_in[8];
    const float* bd  = (const float*)d_in[9];
    const float* bra = (const float*)d_in[10];
    const float* bda = (const float*)d_in[11];
    float* out = (float*)d_out;

    // prep shared: 7*EE ints/floats + 6*NN + 2 ints
    const int psmem = (7 * EE + 6 * NN + 2) * (int)sizeof(int);   // ~53.5 KB
    const int smem  = NN * LT4 * (int)sizeof(float4);             // 105,984 B
    cudaFuncSetAttribute(rd_prep_all, cudaFuncAttributeMaxDynamicSharedMemorySize, psmem);
    cudaFuncSetAttribute(rd_main, cudaFuncAttributeMaxDynamicSharedMemorySize, smem);

    rd_prep_all<<<TT, NTHREADS, psmem>>>(ef, et, wr, wd, wra, wda, br, bd, bra, bda);

    dim3 grid(LL / (LT4 * 4), BB);   // (16, 64)
    rd_main<<<grid, NTHREADS, smem>>>(X, ind, out);
}

// round 5
// speedup vs baseline: 1.5887x; 1.2116x over previous
#include <cuda_runtime.h>

#define NN 207
#define EE 1722
#define TT 24
#define BB 64
#define LL 2048
#define RESV 12
#define L4 (LL / 4)      // 512 float4 per row
#define LT4 32           // float4 per L-tile (= 128 floats)
#define NTHREADS 512     // main kernel: 16 warps, 1 CTA/SM (147 KB smem)
#define NWARPS (NTHREADS / 32)

// ---------------- device scratch (no allocation allowed) ----------------
struct __align__(16) EF { float wrn; float wra; int noff; int pad; };  // wrn = -wr
struct __align__(8)  ET { float wdc; int noff; };

__device__ EF     g_ef[TT * EE];      // from-CSR ordered, per t (reaction gathers)
__device__ ET     g_et[TT * EE];      // to-CSR ordered, per t (diffusion gathers)
__device__ float4 g_c1[TT * NN];      // (dr, dra, dd+dda+1, br)
__device__ float2 g_c2[TT * NN];      // (bra, bd+bda)
__device__ int    g_from_off[NN + 1];
__device__ int    g_to_off[NN + 1];

// ---------------- f32x2 packed helpers ----------------
__device__ __forceinline__ unsigned long long pk2(float a, float b) {
    unsigned long long r;
    asm("mov.b64 %0, {%1, %2};" : "=l"(r) : "f"(a), "f"(b));
    return r;
}
__device__ __forceinline__ void upk2(unsigned long long v, float& a, float& b) {
    asm("mov.b64 {%0, %1}, %2;" : "=f"(a), "=f"(b) : "l"(v));
}
__device__ __forceinline__ void fma2(unsigned long long& d,
                                     unsigned long long a, unsigned long long b) {
    asm("fma.rn.f32x2 %0, %1, %2, %0;" : "+l"(d) : "l"(a), "l"(b));
}
__device__ __forceinline__ float ftanh(float x) {
    float y;
    asm("tanh.approx.f32 %0, %1;" : "=f"(y) : "f"(x));
    return y;
}

// =====================================================================
// Fused prepass: one block per time slot t (deterministic CSR rebuild in
// shared memory, then pack that t's edge records + diagonals).
// =====================================================================
__global__ __launch_bounds__(256)
void rd_prep_all(const int* __restrict__ ef, const int* __restrict__ et,
                 const float* __restrict__ wr,  const float* __restrict__ wd,
                 const float* __restrict__ wra, const float* __restrict__ wda,
                 const float* __restrict__ br,  const float* __restrict__ bd,
                 const float* __restrict__ bra, const float* __restrict__ bda) {
    extern __shared__ int sh[];
    int*   sf    = sh;                 // [EE]
    int*   st    = sf    + EE;         // [EE]
    int*   slotF = st    + EE;         // [EE]
    int*   slotT = slotF + EE;         // [EE]
    float* dsum  = (float*)(slotT + EE);   // [EE] wd+wda by from-slot
    float* rs_r  = dsum  + EE;         // [EE] wr  by to-slot
    float* rs_ra = rs_r  + EE;         // [EE] wra by to-slot
    int*   cntF  = (int*)(rs_ra + EE); // [NN]
    int*   cntT  = cntF + NN;          // [NN]
    int*   offF  = cntT + NN;          // [NN+1]
    int*   offT  = offF + NN + 1;      // [NN+1]
    int*   runF  = offT + NN + 1;      // [NN]
    int*   runT  = runF + NN;          // [NN]

    const int t   = blockIdx.x;
    const int tid = threadIdx.x;
    const int lane = tid & 31;
    const int wid  = tid >> 5;
    const int tE  = t * EE;

    for (int i = tid; i < EE; i += 256) { sf[i] = ef[i]; st[i] = et[i]; }
    for (int i = tid; i < NN; i += 256) { cntF[i] = 0; cntT[i] = 0; runF[i] = 0; runT[i] = 0; }
    __syncthreads();

    for (int i = tid; i < EE; i += 256) {
        atomicAdd(&cntF[sf[i]], 1);
        atomicAdd(&cntT[st[i]], 1);
    }
    __syncthreads();

    // warp 0: exclusive prefix over cntF; warp 1: over cntT
    if (wid < 2) {
        const int* cnt = wid ? cntT : cntF;
        int* off = wid ? offT : offF;
        int carry = 0;
        #pragma unroll
        for (int j = 0; j < (NN + 31) / 32; j++) {
            int idx = j * 32 + lane;
            int v = (idx < NN) ? cnt[idx] : 0;
            int s = v;
            #pragma unroll
            for (int d = 1; d < 32; d <<= 1) {
                int u = __shfl_up_sync(0xffffffffu, s, d);
                if (lane >= d) s += u;
            }
            int tot = __shfl_sync(0xffffffffu, s, 31);
            if (idx < NN) off[idx] = carry + s - v;
            carry += tot;
        }
        if (lane == 0) off[NN] = carry;
    }
    __syncthreads();

    // deterministic slot assignment via match_any ranking (edge-id order)
    if (wid < 2) {
        const int* key = wid ? st : sf;
        const int* off = wid ? offT : offF;
        int* run  = wid ? runT : runF;
        int* slot = wid ? slotT : slotF;
        const int nch = (EE + 31) / 32;
        for (int c = 0; c < nch; c++) {
            int i = c * 32 + lane;
            int f = (i < EE) ? key[i] : (NN + lane);
            unsigned m = __match_any_sync(0xffffffffu, f);
            int leader = __ffs(m) - 1;
            int rank = __popc(m & ((1u << lane) - 1u));
            int base = 0;
            if (lane == leader && f < NN) { base = run[f]; run[f] = base + __popc(m); }
            base = __shfl_sync(0xffffffffu, base, leader);
            if (i < EE) slot[i] = off[f] + base + rank;
        }
    }
    __syncthreads();

    for (int i = tid; i < EE; i += 256) {
        float wrv  = wr[tE + i],  wrav = wra[tE + i];
        float wdv  = wd[tE + i],  wdav = wda[tE + i];
        int sF = slotF[i], sT = slotT[i];
        EF rf; rf.wrn = -wrv; rf.wra = wrav; rf.noff = st[i] * LT4; rf.pad = 0;
        g_ef[tE + sF] = rf;
        ET rt; rt.wdc = wdav - wdv; rt.noff = sf[i] * LT4;
        g_et[tE + sT] = rt;
        dsum[sF]  = wdv + wdav;
        rs_r[sT]  = wrv;
        rs_ra[sT] = wrav;
    }
    __syncthreads();

    if (tid < NN) {
        const int w = tid;
        float dd1 = 0.f;
        for (int k = offF[w]; k < offF[w + 1]; k++) dd1 += dsum[k];
        float dr = 0.f, dra = 0.f;
        for (int k = offT[w]; k < offT[w + 1]; k++) { dr += rs_r[k]; dra += rs_ra[k]; }
        float4 c1; c1.x = dr; c1.y = dra; c1.z = dd1 + 1.f; c1.w = br[t * NN + w];
        g_c1[t * NN + w] = c1;
        float2 c2; c2.x = bra[t * NN + w]; c2.y = bd[t * NN + w] + bda[t * NN + w];
        g_c2[t * NN + w] = c2;
    }

    if (t == 0 && tid <= NN) {
        g_from_off[tid] = offF[tid];
        g_to_off[tid]   = offT[tid];
    }
}

// =====================================================================
// Main kernel: x tile (106 KB) + this t's edge records (41.3 KB) in smem.
// Record reads are broadcast LDS (29 cyc) instead of L2-hit LDG (~250 cyc).
// =====================================================================
__global__ __launch_bounds__(NTHREADS, 1)
void rd_main(const float* __restrict__ X, const int* __restrict__ ind,
             float* __restrict__ out) {
    extern __shared__ float4 xs4[];   // [NN*LT4] x tile, then EF[EE], then ET[EE]
    EF* sef = reinterpret_cast<EF*>(xs4 + NN * LT4);
    ET* set_ = reinterpret_cast<ET*>(sef + EE);
    const ulonglong2* __restrict__ xsp = reinterpret_cast<const ulonglong2*>(xs4);

    const int b   = blockIdx.y;
    const int l0q = blockIdx.x * LT4;
    const int t   = ind[b] / RESV;
    const int tid = threadIdx.x;

    // stage x tile (coalesced DRAM) and record arrays (L2-resident, coalesced)
    const float4* xb4 = reinterpret_cast<const float4*>(X)
                        + (size_t)b * 2 * NN * L4 + l0q;
    for (int idx = tid; idx < NN * LT4; idx += NTHREADS) {
        int w = idx >> 5, c = idx & (LT4 - 1);
        xs4[idx] = xb4[(size_t)w * L4 + c];
    }
    {
        const uint4* src = reinterpret_cast<const uint4*>(g_ef + t * EE);
        uint4* dst = reinterpret_cast<uint4*>(sef);
        for (int i = tid; i < EE; i += NTHREADS) dst[i] = src[i];
        const uint2* src2 = reinterpret_cast<const uint2*>(g_et + t * EE);
        uint2* dst2 = reinterpret_cast<uint2*>(set_);
        for (int i = tid; i < EE; i += NTHREADS) dst2[i] = src2[i];
    }
    __syncthreads();

    const int lane = tid & 31;
    const int wg   = tid >> 5;
    const bool b0  = (b == 0);
    float4* ob4 = reinterpret_cast<float4*>(out) + (size_t)b * NN * L4 + l0q + lane;

    for (int w = wg; w < NN; w += NWARPS) {
        ulonglong2 xw = xsp[w * LT4 + lane];
        float4 c1 = g_c1[t * NN + w];
        float2 c2 = g_c2[t * NN + w];
        float dra = b0 ? 0.f : c1.y;   // batch 0: RWa diagonal is exactly zero

        unsigned long long drp  = pk2(c1.x, c1.x), brp  = pk2(c1.w, c1.w);
        unsigned long long drap = pk2(dra,  dra ), brap = pk2(c2.x, c2.x);
        unsigned long long dlp  = pk2(c1.z, c1.z), bdp  = pk2(c2.y, c2.y);

        unsigned long long r01 = brp,  r23 = brp;
        unsigned long long ra01 = brap, ra23 = brap;
        unsigned long long li01 = bdp,  li23 = bdp;
        fma2(r01, drp, xw.x);   fma2(r23, drp, xw.y);
        fma2(ra01, drap, xw.x); fma2(ra23, drap, xw.y);
        fma2(li01, dlp, xw.x);  fma2(li23, dlp, xw.y);

        int k0 = g_from_off[w], k1 = g_from_off[w + 1];
        #pragma unroll 4
        for (int k = k0; k < k1; k++) {
            EF e = sef[k];                       // broadcast LDS.128
            ulonglong2 xv = xsp[e.noff + lane];  // LDS.128 gather
            unsigned long long wrp  = pk2(e.wrn, e.wrn);
            unsigned long long wrap = pk2(e.wra, e.wra);
            fma2(r01, wrp, xv.x);   fma2(r23, wrp, xv.y);
            fma2(ra01, wrap, xv.x); fma2(ra23, wrap, xv.y);
        }

        k0 = g_to_off[w]; k1 = g_to_off[w + 1];
        #pragma unroll 4
        for (int k = k0; k < k1; k++) {
            ET e = set_[k];                      // broadcast LDS.64
            ulonglong2 xv = xsp[e.noff + lane];
            unsigned long long wdp = pk2(e.wdc, e.wdc);
            fma2(li01, wdp, xv.x); fma2(li23, wdp, xv.y);
        }

        float r0, r1, r2, r3, a0, a1, a2, a3, l0, l1, l2, l3;
        upk2(r01, r0, r1);   upk2(r23, r2, r3);
        upk2(ra01, a0, a1);  upk2(ra23, a2, a3);
        upk2(li01, l0, l1);  upk2(li23, l2, l3);

        float4 o;
        o.x = ftanh(r0) + ftanh(a0) + l0;
        o.y = ftanh(r1) + ftanh(a1) + l1;
        o.z = ftanh(r2) + ftanh(a2) + l2;
        o.w = ftanh(r3) + ftanh(a3) + l3;
        ob4[(size_t)w * L4] = o;
    }
}

// ---------------- launch ----------------
extern "C" void kernel_launch(void* const* d_in, const int* in_sizes, int n_in,
                              void* d_out, int out_size) {
    const float* X   = (const float*)d_in[0];
    const int*   ind = (const int*)d_in[1];
    const int*   ef  = (const int*)d_in[2];
    const int*   et  = (const int*)d_in[3];
    const float* wr  = (const float*)d_in[4];
    const float* wd  = (const float*)d_in[5];
    const float* wra = (const float*)d_in[6];
    const float* wda = (const float*)d_in[7];
    const float* br  = (const float*)d_in[8];
    const float* bd  = (const float*)d_in[9];
    const float* bra = (const float*)d_in[10];
    const float* bda = (const float*)d_in[11];
    float* out = (float*)d_out;

    const int psmem = (7 * EE + 6 * NN + 2) * (int)sizeof(int);   // ~53.5 KB
    const int smem  = NN * LT4 * (int)sizeof(float4)              // 105,984 x tile
                    + EE * (int)sizeof(EF)                        // 27,552 EF
                    + EE * (int)sizeof(ET);                       // 13,776 ET  => 147,312 B
    cudaFuncSetAttribute(rd_prep_all, cudaFuncAttributeMaxDynamicSharedMemorySize, psmem);
    cudaFuncSetAttribute(rd_main, cudaFuncAttributeMaxDynamicSharedMemorySize, smem);

    rd_prep_all<<<TT, 256, psmem>>>(ef, et, wr, wd, wra, wda, br, bd, bra, bda);

    dim3 grid(LL / (LT4 * 4), BB);   // (16, 64)
    rd_main<<<grid, NTHREADS, smem>>>(X, ind, out);
}

// round 6
// speedup vs baseline: 1.8278x; 1.1505x over previous
#include <cuda_runtime.h>

#define NN 207
#define EE 1722
#define TT 24
#define BB 64
#define LL 2048
#define RESV 12
#define L4 (LL / 4)      // 512 float4 per row
#define LT4 32           // float4 per L-tile (= 128 floats)
#define NTHREADS 1024    // main kernel: 32 warps, 1 CTA/SM (152 KB smem)
#define NWARPS (NTHREADS / 32)

// ---------------- device scratch (no allocation allowed) ----------------
struct __align__(16) EF { float wrn; float wra; int noff; int pad; };  // wrn = -wr
struct __align__(8)  ET { float wdc; int noff; };

__device__ EF     g_ef[TT * EE];      // from-CSR ordered, per t (reaction gathers)
__device__ ET     g_et[TT * EE];      // to-CSR ordered, per t (diffusion gathers)
__device__ float4 g_c1[TT * NN];      // (dr, dra, dd+dda+1, br)
__device__ float2 g_c2[TT * NN];      // (bra, bd+bda)
__device__ int    g_from_off[NN + 1];
__device__ int    g_to_off[NN + 1];

// ---------------- f32x2 packed helpers ----------------
__device__ __forceinline__ unsigned long long pk2(float a, float b) {
    unsigned long long r;
    asm("mov.b64 %0, {%1, %2};" : "=l"(r) : "f"(a), "f"(b));
    return r;
}
__device__ __forceinline__ void upk2(unsigned long long v, float& a, float& b) {
    asm("mov.b64 {%0, %1}, %2;" : "=f"(a), "=f"(b) : "l"(v));
}
__device__ __forceinline__ void fma2(unsigned long long& d,
                                     unsigned long long a, unsigned long long b) {
    asm("fma.rn.f32x2 %0, %1, %2, %0;" : "+l"(d) : "l"(a), "l"(b));
}
__device__ __forceinline__ float ftanh(float x) {
    float y;
    asm("tanh.approx.f32 %0, %1;" : "=f"(y) : "f"(x));
    return y;
}

// =====================================================================
// Fused prepass: one block per time slot t (deterministic CSR rebuild in
// shared memory, then pack that t's edge records + diagonals).
// =====================================================================
__global__ __launch_bounds__(256)
void rd_prep_all(const int* __restrict__ ef, const int* __restrict__ et,
                 const float* __restrict__ wr,  const float* __restrict__ wd,
                 const float* __restrict__ wra, const float* __restrict__ wda,
                 const float* __restrict__ br,  const float* __restrict__ bd,
                 const float* __restrict__ bra, const float* __restrict__ bda) {
    extern __shared__ int sh[];
    int*   sf    = sh;                 // [EE]
    int*   st    = sf    + EE;         // [EE]
    int*   slotF = st    + EE;         // [EE]
    int*   slotT = slotF + EE;         // [EE]
    float* dsum  = (float*)(slotT + EE);   // [EE] wd+wda by from-slot
    float* rs_r  = dsum  + EE;         // [EE] wr  by to-slot
    float* rs_ra = rs_r  + EE;         // [EE] wra by to-slot
    int*   cntF  = (int*)(rs_ra + EE); // [NN]
    int*   cntT  = cntF + NN;          // [NN]
    int*   offF  = cntT + NN;          // [NN+1]
    int*   offT  = offF + NN + 1;      // [NN+1]
    int*   runF  = offT + NN + 1;      // [NN]
    int*   runT  = runF + NN;          // [NN]

    const int t   = blockIdx.x;
    const int tid = threadIdx.x;
    const int lane = tid & 31;
    const int wid  = tid >> 5;
    const int tE  = t * EE;

    for (int i = tid; i < EE; i += 256) { sf[i] = ef[i]; st[i] = et[i]; }
    for (int i = tid; i < NN; i += 256) { cntF[i] = 0; cntT[i] = 0; runF[i] = 0; runT[i] = 0; }
    __syncthreads();

    for (int i = tid; i < EE; i += 256) {
        atomicAdd(&cntF[sf[i]], 1);
        atomicAdd(&cntT[st[i]], 1);
    }
    __syncthreads();

    // warp 0: exclusive prefix over cntF; warp 1: over cntT
    if (wid < 2) {
        const int* cnt = wid ? cntT : cntF;
        int* off = wid ? offT : offF;
        int carry = 0;
        #pragma unroll
        for (int j = 0; j < (NN + 31) / 32; j++) {
            int idx = j * 32 + lane;
            int v = (idx < NN) ? cnt[idx] : 0;
            int s = v;
            #pragma unroll
            for (int d = 1; d < 32; d <<= 1) {
                int u = __shfl_up_sync(0xffffffffu, s, d);
                if (lane >= d) s += u;
            }
            int tot = __shfl_sync(0xffffffffu, s, 31);
            if (idx < NN) off[idx] = carry + s - v;
            carry += tot;
        }
        if (lane == 0) off[NN] = carry;
    }
    __syncthreads();

    // deterministic slot assignment via match_any ranking (edge-id order)
    if (wid < 2) {
        const int* key = wid ? st : sf;
        const int* off = wid ? offT : offF;
        int* run  = wid ? runT : runF;
        int* slot = wid ? slotT : slotF;
        const int nch = (EE + 31) / 32;
        for (int c = 0; c < nch; c++) {
            int i = c * 32 + lane;
            int f = (i < EE) ? key[i] : (NN + lane);
            unsigned m = __match_any_sync(0xffffffffu, f);
            int leader = __ffs(m) - 1;
            int rank = __popc(m & ((1u << lane) - 1u));
            int base = 0;
            if (lane == leader && f < NN) { base = run[f]; run[f] = base + __popc(m); }
            base = __shfl_sync(0xffffffffu, base, leader);
            if (i < EE) slot[i] = off[f] + base + rank;
        }
    }
    __syncthreads();

    for (int i = tid; i < EE; i += 256) {
        float wrv  = wr[tE + i],  wrav = wra[tE + i];
        float wdv  = wd[tE + i],  wdav = wda[tE + i];
        int sF = slotF[i], sT = slotT[i];
        EF rf; rf.wrn = -wrv; rf.wra = wrav; rf.noff = st[i] * LT4; rf.pad = 0;
        g_ef[tE + sF] = rf;
        ET rt; rt.wdc = wdav - wdv; rt.noff = sf[i] * LT4;
        g_et[tE + sT] = rt;
        dsum[sF]  = wdv + wdav;
        rs_r[sT]  = wrv;
        rs_ra[sT] = wrav;
    }
    __syncthreads();

    if (tid < NN) {
        const int w = tid;
        float dd1 = 0.f;
        for (int k = offF[w]; k < offF[w + 1]; k++) dd1 += dsum[k];
        float dr = 0.f, dra = 0.f;
        for (int k = offT[w]; k < offT[w + 1]; k++) { dr += rs_r[k]; dra += rs_ra[k]; }
        float4 c1; c1.x = dr; c1.y = dra; c1.z = dd1 + 1.f; c1.w = br[t * NN + w];
        g_c1[t * NN + w] = c1;
        float2 c2; c2.x = bra[t * NN + w]; c2.y = bd[t * NN + w] + bda[t * NN + w];
        g_c2[t * NN + w] = c2;
    }

    if (t == 0 && tid <= NN) {
        g_from_off[tid] = offF[tid];
        g_to_off[tid]   = offT[tid];
    }
}

// =====================================================================
// Main kernel: x tile (106 KB) + this t's edge records (41.3 KB) + row
// coefficients (5 KB) in smem. 1024 threads = 32 warps/SM.
// =====================================================================
__global__ __launch_bounds__(NTHREADS, 1)
void rd_main(const float* __restrict__ X, const int* __restrict__ ind,
             float* __restrict__ out) {
    extern __shared__ float4 xs4[];   // x tile, EF[EE], ET[EE], c1[NN], c2[NN]
    EF*     sef  = reinterpret_cast<EF*>(xs4 + NN * LT4);
    ET*     set_ = reinterpret_cast<ET*>(sef + EE);
    float4* sc1  = reinterpret_cast<float4*>(set_ + EE);
    float2* sc2  = reinterpret_cast<float2*>(sc1 + NN);
    const ulonglong2* __restrict__ xsp = reinterpret_cast<const ulonglong2*>(xs4);

    const int b   = blockIdx.y;
    const int l0q = blockIdx.x * LT4;
    const int t   = ind[b] / RESV;
    const int tid = threadIdx.x;

    // stage x tile (coalesced DRAM) and record arrays (L2-resident, coalesced)
    const float4* xb4 = reinterpret_cast<const float4*>(X)
                        + (size_t)b * 2 * NN * L4 + l0q;
    for (int idx = tid; idx < NN * LT4; idx += NTHREADS) {
        int w = idx >> 5, c = idx & (LT4 - 1);
        xs4[idx] = xb4[(size_t)w * L4 + c];
    }
    {
        const uint4* src = reinterpret_cast<const uint4*>(g_ef + t * EE);
        uint4* dst = reinterpret_cast<uint4*>(sef);
        for (int i = tid; i < EE; i += NTHREADS) dst[i] = src[i];
        const uint2* src2 = reinterpret_cast<const uint2*>(g_et + t * EE);
        uint2* dst2 = reinterpret_cast<uint2*>(set_);
        for (int i = tid; i < EE; i += NTHREADS) dst2[i] = src2[i];
        if (tid < NN) { sc1[tid] = g_c1[t * NN + tid]; sc2[tid] = g_c2[t * NN + tid]; }
    }
    __syncthreads();

    const int lane = tid & 31;
    const int wg   = tid >> 5;
    const bool b0  = (b == 0);
    float4* ob4 = reinterpret_cast<float4*>(out) + (size_t)b * NN * L4 + l0q + lane;

    for (int w = wg; w < NN; w += NWARPS) {
        ulonglong2 xw = xsp[w * LT4 + lane];
        float4 c1 = sc1[w];
        float2 c2 = sc2[w];
        float dra = b0 ? 0.f : c1.y;   // batch 0: RWa diagonal is exactly zero

        unsigned long long drp  = pk2(c1.x, c1.x), brp  = pk2(c1.w, c1.w);
        unsigned long long drap = pk2(dra,  dra ), brap = pk2(c2.x, c2.x);
        unsigned long long dlp  = pk2(c1.z, c1.z), bdp  = pk2(c2.y, c2.y);

        unsigned long long r01 = brp,  r23 = brp;
        unsigned long long ra01 = brap, ra23 = brap;
        unsigned long long li01 = bdp,  li23 = bdp;
        fma2(r01, drp, xw.x);   fma2(r23, drp, xw.y);
        fma2(ra01, drap, xw.x); fma2(ra23, drap, xw.y);
        fma2(li01, dlp, xw.x);  fma2(li23, dlp, xw.y);

        int k0 = g_from_off[w], k1 = g_from_off[w + 1];
        #pragma unroll 4
        for (int k = k0; k < k1; k++) {
            EF e = sef[k];                       // broadcast LDS.128
            ulonglong2 xv = xsp[e.noff + lane];  // LDS.128 gather
            unsigned long long wrp  = pk2(e.wrn, e.wrn);
            unsigned long long wrap = pk2(e.wra, e.wra);
            fma2(r01, wrp, xv.x);   fma2(r23, wrp, xv.y);
            fma2(ra01, wrap, xv.x); fma2(ra23, wrap, xv.y);
        }

        k0 = g_to_off[w]; k1 = g_to_off[w + 1];
        #pragma unroll 4
        for (int k = k0; k < k1; k++) {
            ET e = set_[k];                      // broadcast LDS.64
            ulonglong2 xv = xsp[e.noff + lane];
            unsigned long long wdp = pk2(e.wdc, e.wdc);
            fma2(li01, wdp, xv.x); fma2(li23, wdp, xv.y);
        }

        float r0, r1, r2, r3, a0, a1, a2, a3, l0, l1, l2, l3;
        upk2(r01, r0, r1);   upk2(r23, r2, r3);
        upk2(ra01, a0, a1);  upk2(ra23, a2, a3);
        upk2(li01, l0, l1);  upk2(li23, l2, l3);

        float4 o;
        o.x = ftanh(r0) + ftanh(a0) + l0;
        o.y = ftanh(r1) + ftanh(a1) + l1;
        o.z = ftanh(r2) + ftanh(a2) + l2;
        o.w = ftanh(r3) + ftanh(a3) + l3;
        ob4[(size_t)w * L4] = o;
    }
}

// ---------------- launch ----------------
extern "C" void kernel_launch(void* const* d_in, const int* in_sizes, int n_in,
                              void* d_out, int out_size) {
    const float* X   = (const float*)d_in[0];
    const int*   ind = (const int*)d_in[1];
    const int*   ef  = (const int*)d_in[2];
    const int*   et  = (const int*)d_in[3];
    const float* wr  = (const float*)d_in[4];
    const float* wd  = (const float*)d_in[5];
    const float* wra = (const float*)d_in[6];
    const float* wda = (const float*)d_in[7];
    const float* br  = (const float*)d_in[8];
    const float* bd  = (const float*)d_in[9];
    const float* bra = (const float*)d_in[10];
    const float* bda = (const float*)d_in[11];
    float* out = (float*)d_out;

    const int psmem = (7 * EE + 6 * NN + 2) * (int)sizeof(int);   // ~53.5 KB
    const int smem  = NN * LT4 * (int)sizeof(float4)              // 105,984 x tile
                    + EE * (int)sizeof(EF)                        // 27,552 EF
                    + EE * (int)sizeof(ET)                        // 13,776 ET
                    + NN * (int)sizeof(float4)                    //  3,312 c1
                    + NN * (int)sizeof(float2);                   //  1,656 c2 => 152,280 B
    cudaFuncSetAttribute(rd_prep_all, cudaFuncAttributeMaxDynamicSharedMemorySize, psmem);
    cudaFuncSetAttribute(rd_main, cudaFuncAttributeMaxDynamicSharedMemorySize, smem);

    rd_prep_all<<<TT, 256, psmem>>>(ef, et, wr, wd, wra, wda, br, bd, bra, bda);

    dim3 grid(LL / (LT4 * 4), BB);   // (16, 64)
    rd_main<<<grid, NTHREADS, smem>>>(X, ind, out);
}

// round 7
// speedup vs baseline: 2.2244x; 1.2170x over previous
#include <cuda_runtime.h>

#define NN 207
#define EE 1722
#define TT 24
#define BB 64
#define LL 2048
#define RESV 12
#define L4 (LL / 4)      // 512 float4 per row
#define LT4 32           // float4 per L-tile (= 128 floats)
#define NTHREADS 512     // main kernel: 2 CTAs/SM (101 KB smem each)
#define NWARPS (NTHREADS / 32)

// ---------------- device scratch (no allocation allowed) ----------------
struct __align__(16) EF { float wrn; float wra; int noff; int pad; };  // wrn = -wr
struct __align__(8)  ET { float wdc; int noff; };

__device__ EF     g_ef[TT * EE];      // from-CSR ordered, per t (reaction gathers)
__device__ ET     g_et[TT * EE];      // to-CSR ordered, per t (diffusion gathers)
__device__ float4 g_c1[TT * NN];      // (dr, dra, dd+dda+1, br)
__device__ float2 g_c2[TT * NN];      // (bra, bd+bda)
__device__ int    g_from_off[NN + 1];
__device__ int    g_to_off[NN + 1];

// ---------------- packed helpers ----------------
__device__ __forceinline__ unsigned long long pk2(float a, float b) {
    unsigned long long r;
    asm("mov.b64 %0, {%1, %2};" : "=l"(r) : "f"(a), "f"(b));
    return r;
}
__device__ __forceinline__ void upk2(unsigned long long v, float& a, float& b) {
    asm("mov.b64 {%0, %1}, %2;" : "=f"(a), "=f"(b) : "l"(v));
}
__device__ __forceinline__ void fma2(unsigned long long& d,
                                     unsigned long long a, unsigned long long b) {
    asm("fma.rn.f32x2 %0, %1, %2, %0;" : "+l"(d) : "l"(a), "l"(b));
}
// packed bf16 pair (hi=c1|lo=c0) -> f32x2 {lo=c0, hi=c1}  (bf16 = fp32 high bits)
__device__ __forceinline__ unsigned long long bf2f2(unsigned v) {
    unsigned long long r;
    asm("{\n\t.reg .b32 lo, hi;\n\t"
        "shl.b32 lo, %1, 16;\n\t"
        "and.b32 hi, %1, 0xFFFF0000;\n\t"
        "mov.b64 %0, {lo, hi};\n\t}" : "=l"(r) : "r"(v));
    return r;
}
// pack (c0, c1) fp32 -> bf16x2 (hi=c1, lo=c0), round-to-nearest
__device__ __forceinline__ unsigned f2bf2(float c1, float c0) {
    unsigned r;
    asm("cvt.rn.bf16x2.f32 %0, %1, %2;" : "=r"(r) : "f"(c1), "f"(c0));
    return r;
}
__device__ __forceinline__ float ftanh(float x) {
    float y;
    asm("tanh.approx.f32 %0, %1;" : "=f"(y) : "f"(x));
    return y;
}

// =====================================================================
// Fused prepass: one block per time slot t (deterministic CSR rebuild in
// shared memory, then pack that t's edge records + diagonals).
// =====================================================================
__global__ __launch_bounds__(256)
void rd_prep_all(const int* __restrict__ ef, const int* __restrict__ et,
                 const float* __restrict__ wr,  const float* __restrict__ wd,
                 const float* __restrict__ wra, const float* __restrict__ wda,
                 const float* __restrict__ br,  const float* __restrict__ bd,
                 const float* __restrict__ bra, const float* __restrict__ bda) {
    extern __shared__ int sh[];
    int*   sf    = sh;                 // [EE]
    int*   st    = sf    + EE;         // [EE]
    int*   slotF = st    + EE;         // [EE]
    int*   slotT = slotF + EE;         // [EE]
    float* dsum  = (float*)(slotT + EE);   // [EE] wd+wda by from-slot
    float* rs_r  = dsum  + EE;         // [EE] wr  by to-slot
    float* rs_ra = rs_r  + EE;         // [EE] wra by to-slot
    int*   cntF  = (int*)(rs_ra + EE); // [NN]
    int*   cntT  = cntF + NN;          // [NN]
    int*   offF  = cntT + NN;          // [NN+1]
    int*   offT  = offF + NN + 1;      // [NN+1]
    int*   runF  = offT + NN + 1;      // [NN]
    int*   runT  = runF + NN;          // [NN]

    const int t   = blockIdx.x;
    const int tid = threadIdx.x;
    const int lane = tid & 31;
    const int wid  = tid >> 5;
    const int tE  = t * EE;

    for (int i = tid; i < EE; i += 256) { sf[i] = ef[i]; st[i] = et[i]; }
    for (int i = tid; i < NN; i += 256) { cntF[i] = 0; cntT[i] = 0; runF[i] = 0; runT[i] = 0; }
    __syncthreads();

    for (int i = tid; i < EE; i += 256) {
        atomicAdd(&cntF[sf[i]], 1);
        atomicAdd(&cntT[st[i]], 1);
    }
    __syncthreads();

    // warp 0: exclusive prefix over cntF; warp 1: over cntT
    if (wid < 2) {
        const int* cnt = wid ? cntT : cntF;
        int* off = wid ? offT : offF;
        int carry = 0;
        #pragma unroll
        for (int j = 0; j < (NN + 31) / 32; j++) {
            int idx = j * 32 + lane;
            int v = (idx < NN) ? cnt[idx] : 0;
            int s = v;
            #pragma unroll
            for (int d = 1; d < 32; d <<= 1) {
                int u = __shfl_up_sync(0xffffffffu, s, d);
                if (lane >= d) s += u;
            }
            int tot = __shfl_sync(0xffffffffu, s, 31);
            if (idx < NN) off[idx] = carry + s - v;
            carry += tot;
        }
        if (lane == 0) off[NN] = carry;
    }
    __syncthreads();

    // deterministic slot assignment via match_any ranking (edge-id order)
    if (wid < 2) {
        const int* key = wid ? st : sf;
        const int* off = wid ? offT : offF;
        int* run  = wid ? runT : runF;
        int* slot = wid ? slotT : slotF;
        const int nch = (EE + 31) / 32;
        for (int c = 0; c < nch; c++) {
            int i = c * 32 + lane;
            int f = (i < EE) ? key[i] : (NN + lane);
            unsigned m = __match_any_sync(0xffffffffu, f);
            int leader = __ffs(m) - 1;
            int rank = __popc(m & ((1u << lane) - 1u));
            int base = 0;
            if (lane == leader && f < NN) { base = run[f]; run[f] = base + __popc(m); }
            base = __shfl_sync(0xffffffffu, base, leader);
            if (i < EE) slot[i] = off[f] + base + rank;
        }
    }
    __syncthreads();

    for (int i = tid; i < EE; i += 256) {
        float wrv  = wr[tE + i],  wrav = wra[tE + i];
        float wdv  = wd[tE + i],  wdav = wda[tE + i];
        int sF = slotF[i], sT = slotT[i];
        EF rf; rf.wrn = -wrv; rf.wra = wrav; rf.noff = st[i] * 32; rf.pad = 0;
        g_ef[tE + sF] = rf;
        ET rt; rt.wdc = wdav - wdv; rt.noff = sf[i] * 32;
        g_et[tE + sT] = rt;
        dsum[sF]  = wdv + wdav;
        rs_r[sT]  = wrv;
        rs_ra[sT] = wrav;
    }
    __syncthreads();

    if (tid < NN) {
        const int w = tid;
        float dd1 = 0.f;
        for (int k = offF[w]; k < offF[w + 1]; k++) dd1 += dsum[k];
        float dr = 0.f, dra = 0.f;
        for (int k = offT[w]; k < offT[w + 1]; k++) { dr += rs_r[k]; dra += rs_ra[k]; }
        float4 c1; c1.x = dr; c1.y = dra; c1.z = dd1 + 1.f; c1.w = br[t * NN + w];
        g_c1[t * NN + w] = c1;
        float2 c2; c2.x = bra[t * NN + w]; c2.y = bd[t * NN + w] + bda[t * NN + w];
        g_c2[t * NN + w] = c2;
    }

    if (t == 0 && tid <= NN) {
        g_from_off[tid] = offF[tid];
        g_to_off[tid]   = offT[tid];
    }
}

// =====================================================================
// Main kernel: bf16 x tile (53 KB) + edge records (41 KB) + coefficients
// in smem (~101 KB total) -> 2 CTAs/SM. Gathers are bf16 (2 wf/edge);
// diagonal/passthrough terms use fp32 x read from global (L2-hot).
// =====================================================================
__global__ __launch_bounds__(NTHREADS, 2)
void rd_main(const float* __restrict__ X, const int* __restrict__ ind,
             float* __restrict__ out) {
    extern __shared__ char smem_raw[];
    EF*     sef  = reinterpret_cast<EF*>(smem_raw);                 // [EE]
    uint2*  sxb  = reinterpret_cast<uint2*>(sef + EE);              // [NN*32] bf16 tile
    ET*     set_ = reinterpret_cast<ET*>(sxb + NN * 32);            // [EE]
    float4* sc1  = reinterpret_cast<float4*>(set_ + EE);            // [NN]
    float2* sc2  = reinterpret_cast<float2*>(sc1 + NN);             // [NN]
    int*    soF  = reinterpret_cast<int*>(sc2 + NN);                // [NN+1]
    int*    soT  = soF + NN + 1;                                    // [NN+1]

    const int b   = blockIdx.y;
    const int l0q = blockIdx.x * LT4;
    const int t   = ind[b] / RESV;
    const int tid = threadIdx.x;

    const float4* xb4 = reinterpret_cast<const float4*>(X)
                        + (size_t)b * 2 * NN * L4 + l0q;

    // stage bf16 x tile (convert on the fly) + records + coefficients
    for (int idx = tid; idx < NN * LT4; idx += NTHREADS) {
        int w = idx >> 5, c = idx & (LT4 - 1);
        float4 v = xb4[(size_t)w * L4 + c];
        uint2 p; p.x = f2bf2(v.y, v.x); p.y = f2bf2(v.w, v.z);
        sxb[w * 32 + c] = p;
    }
    {
        const uint4* src = reinterpret_cast<const uint4*>(g_ef + t * EE);
        uint4* dst = reinterpret_cast<uint4*>(sef);
        for (int i = tid; i < EE; i += NTHREADS) dst[i] = src[i];
        const uint2* src2 = reinterpret_cast<const uint2*>(g_et + t * EE);
        uint2* dst2 = reinterpret_cast<uint2*>(set_);
        for (int i = tid; i < EE; i += NTHREADS) dst2[i] = src2[i];
        if (tid < NN) { sc1[tid] = g_c1[t * NN + tid]; sc2[tid] = g_c2[t * NN + tid]; }
        if (tid >= NN && tid < 2 * NN + 2) {
            int j = tid - NN;
            if (j <= NN) { soF[j] = g_from_off[j]; soT[j] = g_to_off[j]; }
        }
        if (tid == 2 * NN + 2) soT[NN] = g_to_off[NN];
    }
    __syncthreads();

    const int lane = tid & 31;
    const int wg   = tid >> 5;
    const bool b0  = (b == 0);
    float4* ob4 = reinterpret_cast<float4*>(out) + (size_t)b * NN * L4 + l0q + lane;

    for (int w = wg; w < NN; w += NWARPS) {
        float4 xw = xb4[(size_t)w * L4 + lane];   // fp32 diag/passthrough (L2-hot)
        float4 c1 = sc1[w];
        float2 c2 = sc2[w];
        float dra = b0 ? 0.f : c1.y;   // batch 0: RWa diagonal is exactly zero

        unsigned long long xw01 = pk2(xw.x, xw.y), xw23 = pk2(xw.z, xw.w);
        unsigned long long drp  = pk2(c1.x, c1.x), brp  = pk2(c1.w, c1.w);
        unsigned long long drap = pk2(dra,  dra ), brap = pk2(c2.x, c2.x);
        unsigned long long dlp  = pk2(c1.z, c1.z), bdp  = pk2(c2.y, c2.y);

        unsigned long long r01 = brp,  r23 = brp;
        unsigned long long ra01 = brap, ra23 = brap;
        unsigned long long li01 = bdp,  li23 = bdp;
        fma2(r01, drp, xw01);   fma2(r23, drp, xw23);
        fma2(ra01, drap, xw01); fma2(ra23, drap, xw23);
        fma2(li01, dlp, xw01);  fma2(li23, dlp, xw23);

        int k0 = soF[w], k1 = soF[w + 1];
        #pragma unroll 4
        for (int k = k0; k < k1; k++) {
            EF e = sef[k];                        // broadcast LDS.128 (1 wf)
            uint2 xv = sxb[e.noff + lane];        // bf16 gather LDS.64 (2 wf)
            unsigned long long x01 = bf2f2(xv.x), x23 = bf2f2(xv.y);
            unsigned long long wrp  = pk2(e.wrn, e.wrn);
            unsigned long long wrap = pk2(e.wra, e.wra);
            fma2(r01, wrp, x01);   fma2(r23, wrp, x23);
            fma2(ra01, wrap, x01); fma2(ra23, wrap, x23);
        }

        k0 = soT[w]; k1 = soT[w + 1];
        #pragma unroll 4
        for (int k = k0; k < k1; k++) {
            ET e = set_[k];                       // broadcast LDS.64 (1 wf)
            uint2 xv = sxb[e.noff + lane];        // bf16 gather LDS.64 (2 wf)
            unsigned long long x01 = bf2f2(xv.x), x23 = bf2f2(xv.y);
            unsigned long long wdp = pk2(e.wdc, e.wdc);
            fma2(li01, wdp, x01); fma2(li23, wdp, x23);
        }

        float r0, r1, r2, r3, a0, a1, a2, a3, l0, l1, l2, l3;
        upk2(r01, r0, r1);   upk2(r23, r2, r3);
        upk2(ra01, a0, a1);  upk2(ra23, a2, a3);
        upk2(li01, l0, l1);  upk2(li23, l2, l3);

        float4 o;
        o.x = ftanh(r0) + ftanh(a0) + l0;
        o.y = ftanh(r1) + ftanh(a1) + l1;
        o.z = ftanh(r2) + ftanh(a2) + l2;
        o.w = ftanh(r3) + ftanh(a3) + l3;
        ob4[(size_t)w * L4] = o;
    }
}

// ---------------- launch ----------------
extern "C" void kernel_launch(void* const* d_in, const int* in_sizes, int n_in,
                              void* d_out, int out_size) {
    const float* X   = (const float*)d_in[0];
    const int*   ind = (const int*)d_in[1];
    const int*   ef  = (const int*)d_in[2];
    const int*   et  = (const int*)d_in[3];
    const float* wr  = (const float*)d_in[4];
    const float* wd  = (const float*)d_in[5];
    const float* wra = (const float*)d_in[6];
    const float* wda = (const float*)d_in[7];
    const float* br  = (const float*)d_in[8];
    const float* bd  = (const float*)d_in[9];
    const float* bra = (const float*)d_in[10];
    const float* bda = (const float*)d_in[11];
    float* out = (float*)d_out;

    const int psmem = (7 * EE + 6 * NN + 2) * (int)sizeof(int);   // ~53.5 KB
    const int smem  = EE * (int)sizeof(EF)          // 27,552 EF
                    + NN * 32 * (int)sizeof(uint2)  // 52,992 bf16 tile
                    + EE * (int)sizeof(ET)          // 13,776 ET
                    + NN * (int)sizeof(float4)      //  3,312 c1
                    + NN * (int)sizeof(float2)      //  1,656 c2
                    + 2 * (NN + 1) * (int)sizeof(int); // 1,664 offsets => 100,952 B
    cudaFuncSetAttribute(rd_prep_all, cudaFuncAttributeMaxDynamicSharedMemorySize, psmem);
    cudaFuncSetAttribute(rd_main, cudaFuncAttributeMaxDynamicSharedMemorySize, smem);

    rd_prep_all<<<TT, 256, psmem>>>(ef, et, wr, wd, wra, wda, br, bd, bra, bda);

    dim3 grid(LL / (LT4 * 4), BB);   // (16, 64)
    rd_main<<<grid, NTHREADS, smem>>>(X, ind, out);
}

// round 8
// speedup vs baseline: 2.3376x; 1.0509x over previous
#include <cuda_runtime.h>

#define NN 207
#define EE 1722
#define TT 24
#define BB 64
#define LL 2048
#define RESV 12
#define L4 (LL / 4)      // 512 float4 per row
#define LT4 32           // float4 per L-tile (= 128 floats)
#define NTHREADS 512     // main kernel: 2 CTAs/SM (101 KB smem each)
#define NWARPS (NTHREADS / 32)

// ---------------- device scratch (no allocation allowed) ----------------
struct __align__(16) EF { float wrn; float wra; int noff; int pad; };  // wrn = -wr, noff = byte offset
struct __align__(8)  ET { float wdc; int noff; };

__device__ EF     g_ef[TT * EE];      // from-CSR ordered, per t (reaction gathers)
__device__ ET     g_et[TT * EE];      // to-CSR ordered, per t (diffusion gathers)
__device__ float4 g_c1[TT * NN];      // (dr, dra, dd+dda+1, br)
__device__ float2 g_c2[TT * NN];      // (bra, bd+bda)
__device__ int    g_from_off[NN + 1];
__device__ int    g_to_off[NN + 1];

// ---------------- packed helpers ----------------
__device__ __forceinline__ unsigned long long pk2(float a, float b) {
    unsigned long long r;
    asm("mov.b64 %0, {%1, %2};" : "=l"(r) : "f"(a), "f"(b));
    return r;
}
__device__ __forceinline__ void upk2(unsigned long long v, float& a, float& b) {
    asm("mov.b64 {%0, %1}, %2;" : "=f"(a), "=f"(b) : "l"(v));
}
__device__ __forceinline__ void fma2(unsigned long long& d,
                                     unsigned long long a, unsigned long long b) {
    asm("fma.rn.f32x2 %0, %1, %2, %0;" : "+l"(d) : "l"(a), "l"(b));
}
// packed bf16 pair (hi=c1|lo=c0) -> f32x2 {lo=c0, hi=c1}  (bf16 = fp32 high bits)
__device__ __forceinline__ unsigned long long bf2f2(unsigned v) {
    unsigned long long r;
    asm("{\n\t.reg .b32 lo, hi;\n\t"
        "shl.b32 lo, %1, 16;\n\t"
        "and.b32 hi, %1, 0xFFFF0000;\n\t"
        "mov.b64 %0, {lo, hi};\n\t}" : "=l"(r) : "r"(v));
    return r;
}
// pack (c0, c1) fp32 -> bf16x2 (hi=c1, lo=c0), round-to-nearest
__device__ __forceinline__ unsigned f2bf2(float c1, float c0) {
    unsigned r;
    asm("cvt.rn.bf16x2.f32 %0, %1, %2;" : "=r"(r) : "f"(c1), "f"(c0));
    return r;
}
__device__ __forceinline__ float ftanh(float x) {
    float y;
    asm("tanh.approx.f32 %0, %1;" : "=f"(y) : "f"(x));
    return y;
}

// =====================================================================
// Fused prepass: one block per time slot t (deterministic CSR rebuild in
// shared memory, then pack that t's edge records + diagonals).
// =====================================================================
__global__ __launch_bounds__(256)
void rd_prep_all(const int* __restrict__ ef, const int* __restrict__ et,
                 const float* __restrict__ wr,  const float* __restrict__ wd,
                 const float* __restrict__ wra, const float* __restrict__ wda,
                 const float* __restrict__ br,  const float* __restrict__ bd,
                 const float* __restrict__ bra, const float* __restrict__ bda) {
    extern __shared__ int sh[];
    int*   sf    = sh;                 // [EE]
    int*   st    = sf    + EE;         // [EE]
    int*   slotF = st    + EE;         // [EE]
    int*   slotT = slotF + EE;         // [EE]
    float* dsum  = (float*)(slotT + EE);   // [EE] wd+wda by from-slot
    float* rs_r  = dsum  + EE;         // [EE] wr  by to-slot
    float* rs_ra = rs_r  + EE;         // [EE] wra by to-slot
    int*   cntF  = (int*)(rs_ra + EE); // [NN]
    int*   cntT  = cntF + NN;          // [NN]
    int*   offF  = cntT + NN;          // [NN+1]
    int*   offT  = offF + NN + 1;      // [NN+1]
    int*   runF  = offT + NN + 1;      // [NN]
    int*   runT  = runF + NN;          // [NN]

    const int t   = blockIdx.x;
    const int tid = threadIdx.x;
    const int lane = tid & 31;
    const int wid  = tid >> 5;
    const int tE  = t * EE;

    for (int i = tid; i < EE; i += 256) { sf[i] = ef[i]; st[i] = et[i]; }
    for (int i = tid; i < NN; i += 256) { cntF[i] = 0; cntT[i] = 0; runF[i] = 0; runT[i] = 0; }
    __syncthreads();

    for (int i = tid; i < EE; i += 256) {
        atomicAdd(&cntF[sf[i]], 1);
        atomicAdd(&cntT[st[i]], 1);
    }
    __syncthreads();

    // warp 0: exclusive prefix over cntF; warp 1: over cntT
    if (wid < 2) {
        const int* cnt = wid ? cntT : cntF;
        int* off = wid ? offT : offF;
        int carry = 0;
        #pragma unroll
        for (int j = 0; j < (NN + 31) / 32; j++) {
            int idx = j * 32 + lane;
            int v = (idx < NN) ? cnt[idx] : 0;
            int s = v;
            #pragma unroll
            for (int d = 1; d < 32; d <<= 1) {
                int u = __shfl_up_sync(0xffffffffu, s, d);
                if (lane >= d) s += u;
            }
            int tot = __shfl_sync(0xffffffffu, s, 31);
            if (idx < NN) off[idx] = carry + s - v;
            carry += tot;
        }
        if (lane == 0) off[NN] = carry;
    }
    __syncthreads();

    // deterministic slot assignment via match_any ranking (edge-id order)
    if (wid < 2) {
        const int* key = wid ? st : sf;
        const int* off = wid ? offT : offF;
        int* run  = wid ? runT : runF;
        int* slot = wid ? slotT : slotF;
        const int nch = (EE + 31) / 32;
        for (int c = 0; c < nch; c++) {
            int i = c * 32 + lane;
            int f = (i < EE) ? key[i] : (NN + lane);
            unsigned m = __match_any_sync(0xffffffffu, f);
            int leader = __ffs(m) - 1;
            int rank = __popc(m & ((1u << lane) - 1u));
            int base = 0;
            if (lane == leader && f < NN) { base = run[f]; run[f] = base + __popc(m); }
            base = __shfl_sync(0xffffffffu, base, leader);
            if (i < EE) slot[i] = off[f] + base + rank;
        }
    }
    __syncthreads();

    for (int i = tid; i < EE; i += 256) {
        float wrv  = wr[tE + i],  wrav = wra[tE + i];
        float wdv  = wd[tE + i],  wdav = wda[tE + i];
        int sF = slotF[i], sT = slotT[i];
        // noff = BYTE offset of the target node's bf16 row (32 uint2 = 256 B)
        EF rf; rf.wrn = -wrv; rf.wra = wrav; rf.noff = st[i] * 256; rf.pad = 0;
        g_ef[tE + sF] = rf;
        ET rt; rt.wdc = wdav - wdv; rt.noff = sf[i] * 256;
        g_et[tE + sT] = rt;
        dsum[sF]  = wdv + wdav;
        rs_r[sT]  = wrv;
        rs_ra[sT] = wrav;
    }
    __syncthreads();

    if (tid < NN) {
        const int w = tid;
        float dd1 = 0.f;
        for (int k = offF[w]; k < offF[w + 1]; k++) dd1 += dsum[k];
        float dr = 0.f, dra = 0.f;
        for (int k = offT[w]; k < offT[w + 1]; k++) { dr += rs_r[k]; dra += rs_ra[k]; }
        float4 c1; c1.x = dr; c1.y = dra; c1.z = dd1 + 1.f; c1.w = br[t * NN + w];
        g_c1[t * NN + w] = c1;
        float2 c2; c2.x = bra[t * NN + w]; c2.y = bd[t * NN + w] + bda[t * NN + w];
        g_c2[t * NN + w] = c2;
    }

    if (t == 0 && tid <= NN) {
        g_from_off[tid] = offF[tid];
        g_to_off[tid]   = offT[tid];
    }
}

// =====================================================================
// Main kernel: bf16 x tile + edge records + coefficients in smem
// (~101 KB) -> 2 CTAs/SM. Row-ahead LDG prefetch, byte-offset gathers,
// unroll 8, cp.async record staging.
// =====================================================================
__global__ __launch_bounds__(NTHREADS, 2)
void rd_main(const float* __restrict__ X, const int* __restrict__ ind,
             float* __restrict__ out) {
    extern __shared__ char smem_raw[];
    EF*     sef  = reinterpret_cast<EF*>(smem_raw);                 // [EE]
    uint2*  sxb  = reinterpret_cast<uint2*>(sef + EE);              // [NN*32] bf16 tile
    ET*     set_ = reinterpret_cast<ET*>(sxb + NN * 32);            // [EE]
    float4* sc1  = reinterpret_cast<float4*>(set_ + EE);            // [NN]
    float2* sc2  = reinterpret_cast<float2*>(sc1 + NN);             // [NN]
    int*    soF  = reinterpret_cast<int*>(sc2 + NN);                // [NN+1]
    int*    soT  = soF + NN + 1;                                    // [NN+1]

    const int b   = blockIdx.y;
    const int l0q = blockIdx.x * LT4;
    const int t   = ind[b] / RESV;
    const int tid = threadIdx.x;

    const float4* xb4 = reinterpret_cast<const float4*>(X)
                        + (size_t)b * 2 * NN * L4 + l0q;

    // ---- stage records via cp.async (overlaps with x conversion below) ----
    {
        unsigned sefA = (unsigned)__cvta_generic_to_shared(sef);
        const char* gef = (const char*)(g_ef + t * EE);
        for (int i = tid; i < EE; i += NTHREADS)
            asm volatile("cp.async.cg.shared.global [%0], [%1], 16;"
                         :: "r"(sefA + i * 16), "l"(gef + (size_t)i * 16));
        unsigned setA = (unsigned)__cvta_generic_to_shared(set_);
        const char* get = (const char*)(g_et + t * EE);
        for (int i = tid; i < EE / 2; i += NTHREADS)   // EE even: 861 x 16 B
            asm volatile("cp.async.cg.shared.global [%0], [%1], 16;"
                         :: "r"(setA + i * 16), "l"(get + (size_t)i * 16));
        asm volatile("cp.async.commit_group;");
    }

    // ---- stage bf16 x tile (convert on the fly) + coefficients ----
    for (int idx = tid; idx < NN * LT4; idx += NTHREADS) {
        int w = idx >> 5, c = idx & (LT4 - 1);
        float4 v = xb4[(size_t)w * L4 + c];
        uint2 p; p.x = f2bf2(v.y, v.x); p.y = f2bf2(v.w, v.z);
        sxb[w * 32 + c] = p;
    }
    if (tid < NN) { sc1[tid] = g_c1[t * NN + tid]; sc2[tid] = g_c2[t * NN + tid]; }
    if (tid >= NN && tid < 2 * NN + 2) {
        int j = tid - NN;
        if (j <= NN) { soF[j] = g_from_off[j]; soT[j] = g_to_off[j]; }
    }
    if (tid == 2 * NN + 2) soT[NN] = g_to_off[NN];

    asm volatile("cp.async.wait_group 0;");
    __syncthreads();

    const int lane = tid & 31;
    const int wg   = tid >> 5;
    const bool b0  = (b == 0);
    float4* ob4 = reinterpret_cast<float4*>(out) + (size_t)b * NN * L4 + l0q + lane;
    const char* sxbase = reinterpret_cast<const char*>(sxb) + lane * 8;

    // row-ahead prefetch of the fp32 diagonal/passthrough vector
    float4 xw = (wg < NN) ? xb4[(size_t)wg * L4 + lane]
                          : make_float4(0.f, 0.f, 0.f, 0.f);

    for (int w = wg; w < NN; w += NWARPS) {
        // kick next row's LDG before the long LDS loops
        int wn = w + NWARPS;
        float4 xwn = xw;
        if (wn < NN) xwn = xb4[(size_t)wn * L4 + lane];

        float4 c1 = sc1[w];
        float2 c2 = sc2[w];
        float dra = b0 ? 0.f : c1.y;   // batch 0: RWa diagonal is exactly zero

        unsigned long long xw01 = pk2(xw.x, xw.y), xw23 = pk2(xw.z, xw.w);
        unsigned long long drp  = pk2(c1.x, c1.x), brp  = pk2(c1.w, c1.w);
        unsigned long long drap = pk2(dra,  dra ), brap = pk2(c2.x, c2.x);
        unsigned long long dlp  = pk2(c1.z, c1.z), bdp  = pk2(c2.y, c2.y);

        unsigned long long r01 = brp,  r23 = brp;
        unsigned long long ra01 = brap, ra23 = brap;
        unsigned long long li01 = bdp,  li23 = bdp;
        fma2(r01, drp, xw01);   fma2(r23, drp, xw23);
        fma2(ra01, drap, xw01); fma2(ra23, drap, xw23);
        fma2(li01, dlp, xw01);  fma2(li23, dlp, xw23);

        int k0 = soF[w], k1 = soF[w + 1];
        #pragma unroll 8
        for (int k = k0; k < k1; k++) {
            EF e = sef[k];                        // broadcast LDS.128 (1 wf)
            uint2 xv = *reinterpret_cast<const uint2*>(sxbase + e.noff);  // 1 IADD + LDS.64
            unsigned long long x01 = bf2f2(xv.x), x23 = bf2f2(xv.y);
            unsigned long long wrp  = pk2(e.wrn, e.wrn);
            unsigned long long wrap = pk2(e.wra, e.wra);
            fma2(r01, wrp, x01);   fma2(r23, wrp, x23);
            fma2(ra01, wrap, x01); fma2(ra23, wrap, x23);
        }

        k0 = soT[w]; k1 = soT[w + 1];
        #pragma unroll 8
        for (int k = k0; k < k1; k++) {
            ET e = set_[k];                       // broadcast LDS.64 (1 wf)
            uint2 xv = *reinterpret_cast<const uint2*>(sxbase + e.noff);
            unsigned long long x01 = bf2f2(xv.x), x23 = bf2f2(xv.y);
            unsigned long long wdp = pk2(e.wdc, e.wdc);
            fma2(li01, wdp, x01); fma2(li23, wdp, x23);
        }

        float r0, r1, r2, r3, a0, a1, a2, a3, l0, l1, l2, l3;
        upk2(r01, r0, r1);   upk2(r23, r2, r3);
        upk2(ra01, a0, a1);  upk2(ra23, a2, a3);
        upk2(li01, l0, l1);  upk2(li23, l2, l3);

        float4 o;
        o.x = ftanh(r0) + ftanh(a0) + l0;
        o.y = ftanh(r1) + ftanh(a1) + l1;
        o.z = ftanh(r2) + ftanh(a2) + l2;
        o.w = ftanh(r3) + ftanh(a3) + l3;
        ob4[(size_t)w * L4] = o;

        xw = xwn;
    }
}

// ---------------- launch ----------------
extern "C" void kernel_launch(void* const* d_in, const int* in_sizes, int n_in,
                              void* d_out, int out_size) {
    const float* X   = (const float*)d_in[0];
    const int*   ind = (const int*)d_in[1];
    const int*   ef  = (const int*)d_in[2];
    const int*   et  = (const int*)d_in[3];
    const float* wr  = (const float*)d_in[4];
    const float* wd  = (const float*)d_in[5];
    const float* wra = (const float*)d_in[6];
    const float* wda = (const float*)d_in[7];
    const float* br  = (const float*)d_in[8];
    const float* bd  = (const float*)d_in[9];
    const float* bra = (const float*)d_in[10];
    const float* bda = (const float*)d_in[11];
    float* out = (float*)d_out;

    const int psmem = (7 * EE + 6 * NN + 2) * (int)sizeof(int);   // ~53.5 KB
    const int smem  = EE * (int)sizeof(EF)          // 27,552 EF
                    + NN * 32 * (int)sizeof(uint2)  // 52,992 bf16 tile
                    + EE * (int)sizeof(ET)          // 13,776 ET
                    + NN * (int)sizeof(float4)      //  3,312 c1
                    + NN * (int)sizeof(float2)      //  1,656 c2
                    + 2 * (NN + 1) * (int)sizeof(int); // 1,664 offsets => 100,952 B
    cudaFuncSetAttribute(rd_prep_all, cudaFuncAttributeMaxDynamicSharedMemorySize, psmem);
    cudaFuncSetAttribute(rd_main, cudaFuncAttributeMaxDynamicSharedMemorySize, smem);

    rd_prep_all<<<TT, 256, psmem>>>(ef, et, wr, wd, wra, wda, br, bd, bra, bda);

    dim3 grid(LL / (LT4 * 4), BB);   // (16, 64)
    rd_main<<<grid, NTHREADS, smem>>>(X, ind, out);
}

// round 9
// speedup vs baseline: 2.3506x; 1.0056x over previous
#include <cuda_runtime.h>

#define NN 207
#define EE 1722
#define TT 24
#define BB 64
#define LL 2048
#define RESV 12
#define L4 (LL / 4)      // 512 float4 per row
#define LT4 32           // float4 per L-tile (= 128 floats)
#define NTHREADS 512     // main kernel: 2 CTAs/SM (101 KB smem each)
#define NWARPS (NTHREADS / 32)

// ---------------- device scratch (no allocation allowed) ----------------
struct __align__(16) EF { float wrn; float wra; int noff; int pad; };  // wrn = -wr, noff = byte offset
struct __align__(8)  ET { float wdc; int noff; };

__device__ EF     g_ef[TT * EE];      // from-CSR ordered, per t (reaction gathers)
__device__ ET     g_et[TT * EE];      // to-CSR ordered, per t (diffusion gathers)
__device__ float4 g_c1[TT * NN];      // (dr, dra, dd+dda+1, br)
__device__ float2 g_c2[TT * NN];      // (bra, bd+bda)
__device__ int    g_from_off[NN + 1];
__device__ int    g_to_off[NN + 1];

// ---------------- packed helpers ----------------
__device__ __forceinline__ unsigned long long pk2(float a, float b) {
    unsigned long long r;
    asm("mov.b64 %0, {%1, %2};" : "=l"(r) : "f"(a), "f"(b));
    return r;
}
__device__ __forceinline__ void upk2(unsigned long long v, float& a, float& b) {
    asm("mov.b64 {%0, %1}, %2;" : "=f"(a), "=f"(b) : "l"(v));
}
__device__ __forceinline__ void fma2(unsigned long long& d,
                                     unsigned long long a, unsigned long long b) {
    asm("fma.rn.f32x2 %0, %1, %2, %0;" : "+l"(d) : "l"(a), "l"(b));
}
// packed bf16 pair (hi=c1|lo=c0) -> f32x2 {lo=c0, hi=c1}  (bf16 = fp32 high bits)
__device__ __forceinline__ unsigned long long bf2f2(unsigned v) {
    unsigned long long r;
    asm("{\n\t.reg .b32 lo, hi;\n\t"
        "shl.b32 lo, %1, 16;\n\t"
        "and.b32 hi, %1, 0xFFFF0000;\n\t"
        "mov.b64 %0, {lo, hi};\n\t}" : "=l"(r) : "r"(v));
    return r;
}
// pack (c0, c1) fp32 -> bf16x2 (hi=c1, lo=c0), round-to-nearest
__device__ __forceinline__ unsigned f2bf2(float c1, float c0) {
    unsigned r;
    asm("cvt.rn.bf16x2.f32 %0, %1, %2;" : "=r"(r) : "f"(c1), "f"(c0));
    return r;
}
__device__ __forceinline__ float ftanh(float x) {
    float y;
    asm("tanh.approx.f32 %0, %1;" : "=f"(y) : "f"(x));
    return y;
}

// =====================================================================
// Fused prepass: one block per time slot t (deterministic CSR rebuild in
// shared memory, then pack that t's edge records + diagonals).
// =====================================================================
__global__ __launch_bounds__(256)
void rd_prep_all(const int* __restrict__ ef, const int* __restrict__ et,
                 const float* __restrict__ wr,  const float* __restrict__ wd,
                 const float* __restrict__ wra, const float* __restrict__ wda,
                 const float* __restrict__ br,  const float* __restrict__ bd,
                 const float* __restrict__ bra, const float* __restrict__ bda) {
    extern __shared__ int sh[];
    int*   sf    = sh;                 // [EE]
    int*   st    = sf    + EE;         // [EE]
    int*   slotF = st    + EE;         // [EE]
    int*   slotT = slotF + EE;         // [EE]
    float* dsum  = (float*)(slotT + EE);   // [EE] wd+wda by from-slot
    float* rs_r  = dsum  + EE;         // [EE] wr  by to-slot
    float* rs_ra = rs_r  + EE;         // [EE] wra by to-slot
    int*   cntF  = (int*)(rs_ra + EE); // [NN]
    int*   cntT  = cntF + NN;          // [NN]
    int*   offF  = cntT + NN;          // [NN+1]
    int*   offT  = offF + NN + 1;      // [NN+1]
    int*   runF  = offT + NN + 1;      // [NN]
    int*   runT  = runF + NN;          // [NN]

    const int t   = blockIdx.x;
    const int tid = threadIdx.x;
    const int lane = tid & 31;
    const int wid  = tid >> 5;
    const int tE  = t * EE;

    for (int i = tid; i < EE; i += 256) { sf[i] = ef[i]; st[i] = et[i]; }
    for (int i = tid; i < NN; i += 256) { cntF[i] = 0; cntT[i] = 0; runF[i] = 0; runT[i] = 0; }
    __syncthreads();

    for (int i = tid; i < EE; i += 256) {
        atomicAdd(&cntF[sf[i]], 1);
        atomicAdd(&cntT[st[i]], 1);
    }
    __syncthreads();

    // warp 0: exclusive prefix over cntF; warp 1: over cntT
    if (wid < 2) {
        const int* cnt = wid ? cntT : cntF;
        int* off = wid ? offT : offF;
        int carry = 0;
        #pragma unroll
        for (int j = 0; j < (NN + 31) / 32; j++) {
            int idx = j * 32 + lane;
            int v = (idx < NN) ? cnt[idx] : 0;
            int s = v;
            #pragma unroll
            for (int d = 1; d < 32; d <<= 1) {
                int u = __shfl_up_sync(0xffffffffu, s, d);
                if (lane >= d) s += u;
            }
            int tot = __shfl_sync(0xffffffffu, s, 31);
            if (idx < NN) off[idx] = carry + s - v;
            carry += tot;
        }
        if (lane == 0) off[NN] = carry;
    }
    __syncthreads();

    // deterministic slot assignment via match_any ranking (edge-id order)
    if (wid < 2) {
        const int* key = wid ? st : sf;
        const int* off = wid ? offT : offF;
        int* run  = wid ? runT : runF;
        int* slot = wid ? slotT : slotF;
        const int nch = (EE + 31) / 32;
        for (int c = 0; c < nch; c++) {
            int i = c * 32 + lane;
            int f = (i < EE) ? key[i] : (NN + lane);
            unsigned m = __match_any_sync(0xffffffffu, f);
            int leader = __ffs(m) - 1;
            int rank = __popc(m & ((1u << lane) - 1u));
            int base = 0;
            if (lane == leader && f < NN) { base = run[f]; run[f] = base + __popc(m); }
            base = __shfl_sync(0xffffffffu, base, leader);
            if (i < EE) slot[i] = off[f] + base + rank;
        }
    }
    __syncthreads();

    for (int i = tid; i < EE; i += 256) {
        float wrv  = wr[tE + i],  wrav = wra[tE + i];
        float wdv  = wd[tE + i],  wdav = wda[tE + i];
        int sF = slotF[i], sT = slotT[i];
        // noff = BYTE offset of the target node's bf16 row (32 uint2 = 256 B)
        EF rf; rf.wrn = -wrv; rf.wra = wrav; rf.noff = st[i] * 256; rf.pad = 0;
        g_ef[tE + sF] = rf;
        ET rt; rt.wdc = wdav - wdv; rt.noff = sf[i] * 256;
        g_et[tE + sT] = rt;
        dsum[sF]  = wdv + wdav;
        rs_r[sT]  = wrv;
        rs_ra[sT] = wrav;
    }
    __syncthreads();

    if (tid < NN) {
        const int w = tid;
        float dd1 = 0.f;
        for (int k = offF[w]; k < offF[w + 1]; k++) dd1 += dsum[k];
        float dr = 0.f, dra = 0.f;
        for (int k = offT[w]; k < offT[w + 1]; k++) { dr += rs_r[k]; dra += rs_ra[k]; }
        float4 c1; c1.x = dr; c1.y = dra; c1.z = dd1 + 1.f; c1.w = br[t * NN + w];
        g_c1[t * NN + w] = c1;
        float2 c2; c2.x = bra[t * NN + w]; c2.y = bd[t * NN + w] + bda[t * NN + w];
        g_c2[t * NN + w] = c2;
    }

    if (t == 0 && tid <= NN) {
        g_from_off[tid] = offF[tid];
        g_to_off[tid]   = offT[tid];
    }
}

// =====================================================================
// Main kernel: each CTA processes TWO 128-column L-tiles, staging the
// edge records (41 KB) ONCE and the bf16 x tile per half. ~101 KB smem,
// 2 CTAs/SM. Row-ahead LDG prefetch, byte-offset gathers, unroll 8.
// =====================================================================
__global__ __launch_bounds__(NTHREADS, 2)
void rd_main(const float* __restrict__ X, const int* __restrict__ ind,
             float* __restrict__ out) {
    extern __shared__ char smem_raw[];
    EF*     sef  = reinterpret_cast<EF*>(smem_raw);                 // [EE]
    uint2*  sxb  = reinterpret_cast<uint2*>(sef + EE);              // [NN*32] bf16 tile
    ET*     set_ = reinterpret_cast<ET*>(sxb + NN * 32);            // [EE]
    float4* sc1  = reinterpret_cast<float4*>(set_ + EE);            // [NN]
    float2* sc2  = reinterpret_cast<float2*>(sc1 + NN);             // [NN]
    int*    soF  = reinterpret_cast<int*>(sc2 + NN);                // [NN+1]
    int*    soT  = soF + NN + 1;                                    // [NN+1]

    const int b   = blockIdx.y;
    const int t   = ind[b] / RESV;
    const int tid = threadIdx.x;
    const int lane = tid & 31;
    const int wg   = tid >> 5;
    const bool b0  = (b == 0);
    const char* sxbase = reinterpret_cast<const char*>(sxb) + lane * 8;

    // ---- stage records via cp.async ONCE for both halves ----
    {
        unsigned sefA = (unsigned)__cvta_generic_to_shared(sef);
        const char* gef = (const char*)(g_ef + t * EE);
        for (int i = tid; i < EE; i += NTHREADS)
            asm volatile("cp.async.cg.shared.global [%0], [%1], 16;"
                         :: "r"(sefA + i * 16), "l"(gef + (size_t)i * 16));
        unsigned setA = (unsigned)__cvta_generic_to_shared(set_);
        const char* get = (const char*)(g_et + t * EE);
        for (int i = tid; i < EE / 2; i += NTHREADS)   // EE even: 861 x 16 B
            asm volatile("cp.async.cg.shared.global [%0], [%1], 16;"
                         :: "r"(setA + i * 16), "l"(get + (size_t)i * 16));
        asm volatile("cp.async.commit_group;");
    }
    if (tid < NN) { sc1[tid] = g_c1[t * NN + tid]; sc2[tid] = g_c2[t * NN + tid]; }
    if (tid >= NN && tid < 2 * NN + 2) {
        int j = tid - NN;
        if (j <= NN) { soF[j] = g_from_off[j]; soT[j] = g_to_off[j]; }
    }
    if (tid == 2 * NN + 2) soT[NN] = g_to_off[NN];

    #pragma unroll 1
    for (int half = 0; half < 2; half++) {
        const int l0q = (blockIdx.x * 2 + half) * LT4;
        const float4* xb4 = reinterpret_cast<const float4*>(X)
                            + (size_t)b * 2 * NN * L4 + l0q;

        // ---- stage bf16 x tile for this half ----
        for (int idx = tid; idx < NN * LT4; idx += NTHREADS) {
            int w = idx >> 5, c = idx & (LT4 - 1);
            float4 v = xb4[(size_t)w * L4 + c];
            uint2 p; p.x = f2bf2(v.y, v.x); p.y = f2bf2(v.w, v.z);
            sxb[w * 32 + c] = p;
        }
        if (half == 0) asm volatile("cp.async.wait_group 0;");
        __syncthreads();

        float4* ob4 = reinterpret_cast<float4*>(out) + (size_t)b * NN * L4 + l0q + lane;

        // row-ahead prefetch of the fp32 diagonal/passthrough vector
        float4 xw = (wg < NN) ? xb4[(size_t)wg * L4 + lane]
                              : make_float4(0.f, 0.f, 0.f, 0.f);

        for (int w = wg; w < NN; w += NWARPS) {
            // kick next row's LDG before the long LDS loops
            int wn = w + NWARPS;
            float4 xwn = xw;
            if (wn < NN) xwn = xb4[(size_t)wn * L4 + lane];

            float4 c1 = sc1[w];
            float2 c2 = sc2[w];
            float dra = b0 ? 0.f : c1.y;   // batch 0: RWa diagonal is exactly zero

            unsigned long long xw01 = pk2(xw.x, xw.y), xw23 = pk2(xw.z, xw.w);
            unsigned long long drp  = pk2(c1.x, c1.x), brp  = pk2(c1.w, c1.w);
            unsigned long long drap = pk2(dra,  dra ), brap = pk2(c2.x, c2.x);
            unsigned long long dlp  = pk2(c1.z, c1.z), bdp  = pk2(c2.y, c2.y);

            unsigned long long r01 = brp,  r23 = brp;
            unsigned long long ra01 = brap, ra23 = brap;
            unsigned long long li01 = bdp,  li23 = bdp;
            fma2(r01, drp, xw01);   fma2(r23, drp, xw23);
            fma2(ra01, drap, xw01); fma2(ra23, drap, xw23);
            fma2(li01, dlp, xw01);  fma2(li23, dlp, xw23);

            int k0 = soF[w], k1 = soF[w + 1];
            #pragma unroll 8
            for (int k = k0; k < k1; k++) {
                EF e = sef[k];                        // broadcast LDS.128 (1 wf)
                uint2 xv = *reinterpret_cast<const uint2*>(sxbase + e.noff);
                unsigned long long x01 = bf2f2(xv.x), x23 = bf2f2(xv.y);
                unsigned long long wrp  = pk2(e.wrn, e.wrn);
                unsigned long long wrap = pk2(e.wra, e.wra);
                fma2(r01, wrp, x01);   fma2(r23, wrp, x23);
                fma2(ra01, wrap, x01); fma2(ra23, wrap, x23);
            }

            k0 = soT[w]; k1 = soT[w + 1];
            #pragma unroll 8
            for (int k = k0; k < k1; k++) {
                ET e = set_[k];                       // broadcast LDS.64 (1 wf)
                uint2 xv = *reinterpret_cast<const uint2*>(sxbase + e.noff);
                unsigned long long x01 = bf2f2(xv.x), x23 = bf2f2(xv.y);
                unsigned long long wdp = pk2(e.wdc, e.wdc);
                fma2(li01, wdp, x01); fma2(li23, wdp, x23);
            }

            float r0, r1, r2, r3, a0, a1, a2, a3, l0, l1, l2, l3;
            upk2(r01, r0, r1);   upk2(r23, r2, r3);
            upk2(ra01, a0, a1);  upk2(ra23, a2, a3);
            upk2(li01, l0, l1);  upk2(li23, l2, l3);

            float4 o;
            o.x = ftanh(r0) + ftanh(a0) + l0;
            o.y = ftanh(r1) + ftanh(a1) + l1;
            o.z = ftanh(r2) + ftanh(a2) + l2;
            o.w = ftanh(r3) + ftanh(a3) + l3;
            ob4[(size_t)w * L4] = o;

            xw = xwn;
        }
        __syncthreads();   // all reads of sxb done before half=1 overwrites it
    }
}

// ---------------- launch ----------------
extern "C" void kernel_launch(void* const* d_in, const int* in_sizes, int n_in,
                              void* d_out, int out_size) {
    const float* X   = (const float*)d_in[0];
    const int*   ind = (const int*)d_in[1];
    const int*   ef  = (const int*)d_in[2];
    const int*   et  = (const int*)d_in[3];
    const float* wr  = (const float*)d_in[4];
    const float* wd  = (const float*)d_in[5];
    const float* wra = (const float*)d_in[6];
    const float* wda = (const float*)d_in[7];
    const float* br  = (const float*)d_in[8];
    const float* bd  = (const float*)d_in[9];
    const float* bra = (const float*)d_in[10];
    const float* bda = (const float*)d_in[11];
    float* out = (float*)d_out;

    const int psmem = (7 * EE + 6 * NN + 2) * (int)sizeof(int);   // ~53.5 KB
    const int smem  = EE * (int)sizeof(EF)          // 27,552 EF
                    + NN * 32 * (int)sizeof(uint2)  // 52,992 bf16 tile
                    + EE * (int)sizeof(ET)          // 13,776 ET
                    + NN * (int)sizeof(float4)      //  3,312 c1
                    + NN * (int)sizeof(float2)      //  1,656 c2
                    + 2 * (NN + 1) * (int)sizeof(int); // 1,664 offsets => 100,952 B
    cudaFuncSetAttribute(rd_prep_all, cudaFuncAttributeMaxDynamicSharedMemorySize, psmem);
    cudaFuncSetAttribute(rd_main, cudaFuncAttributeMaxDynamicSharedMemorySize, smem);

    rd_prep_all<<<TT, 256, psmem>>>(ef, et, wr, wd, wra, wda, br, bd, bra, bda);

    dim3 grid(LL / (LT4 * 4 * 2), BB);   // (8, 64) — two L-tiles per CTA
    rd_main<<<grid, NTHREADS, smem>>>(X, ind, out);
}